// round 4
// baseline (speedup 1.0000x reference)
#include <cuda_runtime.h>
#include <cuda_bf16.h>
#include <math.h>

#define TTOT 131072
#define SCALE 0.17677669529663687f
#define GN_N 1048576.0f

typedef unsigned long long ull;

__device__ __forceinline__ ull pack2(float a, float b) {
    ull r; asm("mov.b64 %0, {%1, %2};" : "=l"(r) : "f"(a), "f"(b)); return r;
}
__device__ __forceinline__ void unpack2(ull p, float& a, float& b) {
    asm("mov.b64 {%0, %1}, %2;" : "=f"(a), "=f"(b) : "l"(p));
}
__device__ __forceinline__ void ffma2(ull& d, ull a, ull b) {
    asm("fma.rn.f32x2 %0, %1, %2, %0;" : "+l"(d) : "l"(a), "l"(b));
}

// ---------------- scratch ----------------
__device__ float g_q   [(size_t)TTOT*256];
__device__ float g_k   [(size_t)TTOT*256];
__device__ float g_v   [(size_t)TTOT*256];
__device__ float g_qa  [(size_t)TTOT*256];
__device__ float g_ka  [(size_t)TTOT*256];
__device__ float g_ul  [(size_t)TTOT*128];
__device__ float g_y1  [(size_t)TTOT*256];
__device__ float g_y2  [(size_t)TTOT*192];
__device__ float g_attout[(size_t)TTOT*256];
__device__ float g_wqkv_t [256*768];
__device__ float g_wsq_t  [256*128];
__device__ float g_wgwcp_t[2*352*128];
__device__ float g_wpwc2_t[64*192];
__device__ float g_wout_t [256*256];
__device__ float g_gnstats[2*16*2];
__device__ float g_pool[2*512];
__device__ float g_misc[4];

// ---------------- small utility kernels ----------------
__global__ void zero_small() {
    int i = blockIdx.x*256 + threadIdx.x;
    if (i < 1024) g_pool[i] = 0.f;
    if (i < 64)   g_gnstats[i] = 0.f;
}

__global__ void transpose_w(const float* __restrict__ in, float* __restrict__ out, int N, int K) {
    int i = blockIdx.x*256 + threadIdx.x;
    if (i >= N*K) return;
    int n = i % N, k = i / N;
    out[i] = in[n*K + k];
}

__global__ void make_sq(const float* __restrict__ sq1, const float* __restrict__ sq2) {
    int i = blockIdx.x*256 + threadIdx.x;
    if (i >= 256*128) return;
    int n = i & 127, k = i >> 7;
    float v = 0.f;
    if (n < 64)  { if (k < 128)  v = sq1[n*128 + k]; }
    else         { if (k >= 128) v = sq2[(n-64)*128 + (k-128)]; }
    g_wsq_t[i] = v;
}

__global__ void make_gwcp(const float* __restrict__ gwc, const float* __restrict__ pwc1) {
    int i = blockIdx.x*256 + threadIdx.x;
    if (i >= 2*352*128) return;
    int z = i / 45056, r = i % 45056;
    int k = r >> 7, n = r & 127;
    int c = z*128 + n;
    g_wgwcp_t[i] = (k < 288) ? gwc[c*288 + k] : pwc1[c*64 + (k - 288)];
}

__global__ void sum_gnw(const float* __restrict__ gn_w) {
    __shared__ float sh[256];
    sh[threadIdx.x] = gn_w[threadIdx.x];
    __syncthreads();
    for (int st = 128; st > 0; st >>= 1) {
        if (threadIdx.x < st) sh[threadIdx.x] += sh[threadIdx.x + st];
        __syncthreads();
    }
    if (threadIdx.x == 0) g_misc[0] = sh[0];
}

// ---------------- generic 128x128x16 SGEMM (f32x2) ----------------
template<class AF, class EF>
__global__ __launch_bounds__(256, 2) void sgemm_k(AF af, const float* __restrict__ Bt,
                                                  int bstride, EF ef, int N, int K) {
    __shared__ __align__(16) float As[16][128];
    __shared__ __align__(16) float Bs[16][128];
    int z = blockIdx.z;
    const float* B = Bt + (size_t)z * bstride;
    int m0 = blockIdx.y << 7, n0 = blockIdx.x << 7;
    int tid = threadIdx.x;
    int r0 = (tid >> 4) << 3, c0 = (tid & 15) << 3;
    ull acc2[8][4];
    ull zz = pack2(0.f, 0.f);
#pragma unroll
    for (int i = 0; i < 8; i++)
#pragma unroll
        for (int j = 0; j < 4; j++) acc2[i][j] = zz;

    for (int k0 = 0; k0 < K; k0 += 16) {
#pragma unroll
        for (int i = 0; i < 8; i++) {
            int idx = (i << 8) + tid;
            int rr = idx & 127, kk = idx >> 7;
            As[kk][rr] = af(m0 + rr, k0 + kk, z);
        }
#pragma unroll
        for (int i = 0; i < 8; i++) {
            int idx = (i << 8) + tid;
            int cc = idx & 127, kk = idx >> 7;
            int n = n0 + cc;
            Bs[kk][cc] = (n < N) ? B[(size_t)(k0 + kk)*N + n] : 0.f;
        }
        __syncthreads();
#pragma unroll
        for (int kk = 0; kk < 16; kk++) {
            float4 a0 = *(const float4*)&As[kk][r0];
            float4 a1 = *(const float4*)&As[kk][r0 + 4];
            const ull* bp = (const ull*)&Bs[kk][c0];
            ull b0 = bp[0], b1 = bp[1], b2 = bp[2], b3 = bp[3];
            float av[8] = {a0.x, a0.y, a0.z, a0.w, a1.x, a1.y, a1.z, a1.w};
#pragma unroll
            for (int i = 0; i < 8; i++) {
                ull ai = pack2(av[i], av[i]);
                ffma2(acc2[i][0], ai, b0);
                ffma2(acc2[i][1], ai, b1);
                ffma2(acc2[i][2], ai, b2);
                ffma2(acc2[i][3], ai, b3);
            }
        }
        __syncthreads();
    }
    float psum[8];
    if (EF::HAS_POOL) {
#pragma unroll
        for (int j = 0; j < 8; j++) psum[j] = 0.f;
    }
#pragma unroll
    for (int i = 0; i < 8; i++) {
        int m = m0 + r0 + i;
#pragma unroll
        for (int j = 0; j < 4; j++) {
            float lo, hi;
            unpack2(acc2[i][j], lo, hi);
            int n = n0 + c0 + 2*j;
            if (n < N)     ef(m, n,     z, lo);
            if (n + 1 < N) ef(m, n + 1, z, hi);
            if (EF::HAS_POOL) { psum[2*j] += lo; psum[2*j+1] += hi; }
        }
    }
    if (EF::HAS_POOL) {
        float* red = &As[0][0];
        __syncthreads();
#pragma unroll
        for (int j = 0; j < 8; j++) red[(tid >> 4)*128 + c0 + j] = psum[j];
        __syncthreads();
        if (tid < 128) {
            int n = n0 + tid;
            float s = 0.f;
#pragma unroll
            for (int r = 0; r < 16; r++) s += red[r*128 + tid];
            if (n < N) {
                int slot = ef.pslot(n, z, m0 >> 16);
                if (slot >= 0) atomicAdd(&g_pool[slot], s);
            }
        }
    }
}

// ---------------- A loaders ----------------
struct AQKV {
    const float* x;
    __device__ float operator()(int t, int k, int z) const {
        int b = t >> 16, pixi = t & 65535;
        int hr = pixi >> 8, wr = pixi & 255;
        return x[(size_t)((b << 8) + k)*65536 + (((hr + 4) & 255) << 8) + ((wr + 4) & 255)];
    }
};
struct AKtok {
    __device__ float operator()(int t, int k, int z) const { return g_k[(size_t)t*256 + k]; }
};
struct ALow {
    __device__ float operator()(int t, int k, int z) const { return g_ul[(size_t)t*128 + 64 + k]; }
};
struct AConvP {
    __device__ float operator()(int t, int k, int z) const {
        if (k >= 288) return g_ul[(size_t)t*128 + (k - 288)];
        int kl = k / 9;
        int tap = k - kl*9;
        int kin = (z << 5) + kl;
        int dy = tap/3 - 1, dx = tap - (tap/3)*3 - 1;
        int b = t >> 16, pixi = t & 65535;
        int hr = (pixi >> 8) + dy, wr = (pixi & 255) + dx;
        if ((unsigned)hr > 255u || (unsigned)wr > 255u) return 0.f;
        return g_ul[(size_t)((b << 16) + (hr << 8) + wr)*128 + kin];
    }
};

// ---------------- epilogues ----------------
struct EQKV {
    static constexpr bool HAS_POOL = false;
    const float* bias;
    __device__ void operator()(int t, int n, int z, float v) const {
        v += bias[n];
        if (n < 256)      g_q[(size_t)t*256 + n] = v;
        else if (n < 512) g_k[(size_t)t*256 + (n - 256)] = v;
        else              g_v[(size_t)t*256 + (n - 512)] = v;
    }
    __device__ int pslot(int n, int z, int b) const { return -1; }
};
struct EUL {
    static constexpr bool HAS_POOL = true;
    __device__ void operator()(int t, int n, int z, float v) const { g_ul[(size_t)t*128 + n] = v; }
    __device__ int pslot(int n, int z, int b) const { return n >= 64 ? (b << 9) + 448 + (n - 64) : -1; }
};
struct EY1 {
    static constexpr bool HAS_POOL = true;
    const float* bias;
    __device__ void operator()(int t, int n, int z, float v) const {
        int c = (z << 7) + n;
        g_y1[(size_t)t*256 + c] = v + bias[c];
    }
    __device__ int pslot(int n, int z, int b) const { return (b << 9) + (z << 7) + n; }
};
struct EY2 {
    static constexpr bool HAS_POOL = true;
    __device__ void operator()(int t, int n, int z, float v) const { g_y2[(size_t)t*192 + n] = v; }
    __device__ int pslot(int n, int z, int b) const { return (b << 9) + 256 + n; }
};

// EY1 pool must include its bias contribution: pooled mean of (gemm+bias).
// We add bias*65536/65536 = bias at softmax input time instead: simpler to fold here.
// (bias is added per-element in EY1 already, but psum is computed from raw acc;
//  compensate by adding bias[c] once per token count at softmax — handled below.)

// ---------------- GroupNorm stats (token-major) ----------------
__global__ void gn_stats() {
    int t0 = blockIdx.x * 512;
    int c = threadIdx.x;
    const float* p = g_q + (size_t)t0*256 + c;
    float s = 0.f, s2 = 0.f;
#pragma unroll 4
    for (int i = 0; i < 512; i++) {
        float v = p[(size_t)i*256];
        s += v; s2 += v*v;
    }
#pragma unroll
    for (int off = 8; off > 0; off >>= 1) {
        s  += __shfl_down_sync(0xffffffff, s,  off, 16);
        s2 += __shfl_down_sync(0xffffffff, s2, off, 16);
    }
    if ((c & 15) == 0) {
        int b = t0 >> 16, g = c >> 4;
        atomicAdd(&g_gnstats[((b << 4) + g)*2],     s);
        atomicAdd(&g_gnstats[((b << 4) + g)*2 + 1], s2);
    }
}

// ---------------- SRU (pure elementwise, token-major) ----------------
__global__ void sru_elem(const float* __restrict__ gn_w, const float* __restrict__ gn_b) {
    int i = blockIdx.x*256 + threadIdx.x;   // over TTOT*128
    int t = i >> 7, cp = i & 127;
    int b = t >> 16;
    int c1 = cp, c2 = cp + 128;
    float wsum = g_misc[0];
    int g1 = c1 >> 4, g2 = c2 >> 4;
    float m1 = g_gnstats[((b<<4)+g1)*2] / GN_N;
    float v1 = g_gnstats[((b<<4)+g1)*2+1] / GN_N - m1*m1;
    float m2 = g_gnstats[((b<<4)+g2)*2] / GN_N;
    float v2 = g_gnstats[((b<<4)+g2)*2+1] / GN_N - m2*m2;
    float w1c = gn_w[c1], w2c = gn_w[c2];
    float A1 = rsqrtf(v1 + 1e-5f)*w1c, B1 = gn_b[c1] - m1*rsqrtf(v1 + 1e-5f)*w1c;
    float A2 = rsqrtf(v2 + 1e-5f)*w2c, B2 = gn_b[c2] - m2*rsqrtf(v2 + 1e-5f)*w2c;
    float x1 = g_q[(size_t)t*256 + c1], x2 = g_q[(size_t)t*256 + c2];
    float rw1 = 1.0f/(1.0f + expf(-(x1*A1 + B1)*(w1c/wsum)));
    float rw2 = 1.0f/(1.0f + expf(-(x2*A2 + B2)*(w2c/wsum)));
    float w11 = rw1 > 0.5f ? 1.0f : rw1, w21 = rw1 > 0.5f ? 0.0f : rw1;
    float w12 = rw2 > 0.5f ? 1.0f : rw2, w22 = rw2 > 0.5f ? 0.0f : rw2;
    g_qa[(size_t)t*256 + c1] = w11*x1 + w22*x2;
    g_qa[(size_t)t*256 + c2] = w12*x2 + w21*x1;
}

// ---------------- softmax over pooled (with EY1-bias correction) ----------------
__global__ void softmax512(const float* __restrict__ gwc_b) {
    int b = blockIdx.x, t = threadIdx.x;
    __shared__ float sh[512];
    float v = g_pool[(b << 9) + t] * (1.0f/65536.0f);
    // EY1's pool reduction summed raw GEMM accs; y1 includes +gwc_b[c]. Add it back.
    if (t < 256) v += gwc_b[t];
    sh[t] = v;
    __syncthreads();
    for (int st = 256; st > 0; st >>= 1) { if (t < st) sh[t] = fmaxf(sh[t], sh[t + st]); __syncthreads(); }
    float mx = sh[0];
    __syncthreads();
    float e = expf(v - mx);
    sh[t] = e;
    __syncthreads();
    for (int st = 256; st > 0; st >>= 1) { if (t < st) sh[t] += sh[t + st]; __syncthreads(); }
    float sum = sh[0];
    __syncthreads();
    g_pool[(b << 9) + t] = e / sum;
}

__global__ void cru_combine() {
    int i = blockIdx.x*256 + threadIdx.x;
    int t = i >> 8, c = i & 255;
    int b = t >> 16;
    float y1 = g_y1[i];
    float y2v = (c < 192) ? g_y2[(size_t)t*192 + c] : g_ul[(size_t)t*128 + 64 + (c - 192)];
    float s1 = g_pool[(b << 9) + c], s2 = g_pool[(b << 9) + 256 + c];
    g_ka[(size_t)t*256 + c] = s1*y1 + s2*y2v;
}

// ---------------- windowed attention (token-major gather) ----------------
__global__ __launch_bounds__(64) void attn(const float* __restrict__ rel_pos) {
    int win = blockIdx.x, h = blockIdx.y, b = blockIdx.z;
    __shared__ __align__(16) float ksh[2048];
    __shared__ __align__(16) float vsh[2048];
    __shared__ float rp[225];
    int wy = win >> 5, wx = win & 31;
    int t0 = (b << 16) + (wy << 11) + (wx << 3);  // token of window origin
    int tid = threadIdx.x;
    int hb = h << 5;
    for (int i = tid; i < 2048; i += 64) {
        int p = i >> 5, d = i & 31;
        int t = t0 + ((p >> 3) << 8) + (p & 7);
        ksh[i] = g_ka[(size_t)t*256 + hb + d];
        vsh[i] = g_v [(size_t)t*256 + hb + d];
    }
    for (int i = tid; i < 225; i += 64) rp[i] = rel_pos[h*225 + i];
    __syncthreads();

    int myt = t0 + ((tid >> 3) << 8) + (tid & 7);
    ull qp[16];
#pragma unroll
    for (int d = 0; d < 16; d++) {
        float2 qv = *(const float2*)&g_qa[(size_t)myt*256 + hb + 2*d];
        qp[d] = pack2(qv.x, qv.y);
    }
    int ph = tid >> 3, pw = tid & 7;
    bool lr = wy == 31, lc = wx == 31;
    ull zz = pack2(0.f, 0.f);

    float s[64];
#pragma unroll
    for (int qi = 0; qi < 64; qi++) {
        const ull* kp = (const ull*)&ksh[qi*32];
        ull dp = zz;
#pragma unroll
        for (int d = 0; d < 16; d++) ffma2(dp, qp[d], kp[d]);
        float dl, dh;
        unpack2(dp, dl, dh);
        float dot = dl + dh;
        int qh = qi >> 3, qw = qi & 7;
        float val = dot*SCALE + rp[(ph - qh + 7)*15 + (pw - qw + 7)];
        if ((lr && ((ph < 4) != (qh < 4))) || (lc && ((pw < 4) != (qw < 4)))) val = -1e30f;
        s[qi] = val;
    }
    float mx = -1e30f;
#pragma unroll
    for (int qi = 0; qi < 64; qi++) mx = fmaxf(mx, s[qi]);
    float sum = 0.f;
#pragma unroll
    for (int qi = 0; qi < 64; qi++) { s[qi] = expf(s[qi] - mx); sum += s[qi]; }
    float inv = 1.0f / sum;
    ull accp[16];
#pragma unroll
    for (int d = 0; d < 16; d++) accp[d] = zz;
#pragma unroll
    for (int qi = 0; qi < 64; qi++) {
        float w = s[qi]*inv;
        ull wd = pack2(w, w);
        const ull* vp = (const ull*)&vsh[qi*32];
#pragma unroll
        for (int d = 0; d < 16; d++) ffma2(accp[d], wd, vp[d]);
    }
    float* o = g_attout + (size_t)myt*256 + hb;
#pragma unroll
    for (int d = 0; d < 16; d++) {
        float lo, hi;
        unpack2(accp[d], lo, hi);
        o[2*d] = lo; o[2*d + 1] = hi;
    }
}

// ---------------- out-projection GEMM with staged NCHW writes ----------------
__global__ __launch_bounds__(256, 2) void sgemm_out(const float* __restrict__ Bt,
                                                    const float* __restrict__ bias,
                                                    float* __restrict__ out) {
    __shared__ __align__(16) float As[16][128];
    __shared__ __align__(16) float Bs[16][128];
    __shared__ float stage[32][129];
    int m0 = blockIdx.y << 7, n0 = blockIdx.x << 7;
    int tid = threadIdx.x;
    int r0 = (tid >> 4) << 3, c0 = (tid & 15) << 3;
    ull acc2[8][4];
    ull zz = pack2(0.f, 0.f);
#pragma unroll
    for (int i = 0; i < 8; i++)
#pragma unroll
        for (int j = 0; j < 4; j++) acc2[i][j] = zz;

    for (int k0 = 0; k0 < 256; k0 += 16) {
#pragma unroll
        for (int i = 0; i < 8; i++) {
            int idx = (i << 8) + tid;
            int rr = idx & 127, kk = idx >> 7;
            As[kk][rr] = g_attout[(size_t)(m0 + rr)*256 + k0 + kk];
        }
#pragma unroll
        for (int i = 0; i < 8; i++) {
            int idx = (i << 8) + tid;
            int cc = idx & 127, kk = idx >> 7;
            Bs[kk][cc] = Bt[(size_t)(k0 + kk)*256 + n0 + cc];
        }
        __syncthreads();
#pragma unroll
        for (int kk = 0; kk < 16; kk++) {
            float4 a0 = *(const float4*)&As[kk][r0];
            float4 a1 = *(const float4*)&As[kk][r0 + 4];
            const ull* bp = (const ull*)&Bs[kk][c0];
            ull b0 = bp[0], b1 = bp[1], b2 = bp[2], b3 = bp[3];
            float av[8] = {a0.x, a0.y, a0.z, a0.w, a1.x, a1.y, a1.z, a1.w};
#pragma unroll
            for (int i = 0; i < 8; i++) {
                ull ai = pack2(av[i], av[i]);
                ffma2(acc2[i][0], ai, b0);
                ffma2(acc2[i][1], ai, b1);
                ffma2(acc2[i][2], ai, b2);
                ffma2(acc2[i][3], ai, b3);
            }
        }
        __syncthreads();
    }
#pragma unroll
    for (int chunk = 0; chunk < 4; chunk++) {
        if ((r0 >> 5) == chunk) {
            int rb = r0 & 31;
#pragma unroll
            for (int i = 0; i < 8; i++)
#pragma unroll
                for (int j = 0; j < 4; j++) {
                    float lo, hi;
                    unpack2(acc2[i][j], lo, hi);
                    stage[rb + i][c0 + 2*j]     = lo;
                    stage[rb + i][c0 + 2*j + 1] = hi;
                }
        }
        __syncthreads();
        int lane = tid & 31;
        int m = m0 + (chunk << 5) + lane;
        int b = m >> 16, pixi = m & 65535;
        int hr = pixi >> 8, wr = pixi & 255;
        size_t pbase = (size_t)(((hr + 4) & 255) << 8) + ((wr + 4) & 255);
        for (int nl = tid >> 5; nl < 128; nl += 8) {
            int n = n0 + nl;
            out[(size_t)((b << 8) + n)*65536 + pbase] = stage[lane][nl] + bias[n];
        }
        __syncthreads();
    }
}

// ---------------- launch ----------------
extern "C" void kernel_launch(void* const* d_in, const int* in_sizes, int n_in,
                              void* d_out, int out_size) {
    const float* x      = (const float*)d_in[0];
    const float* w_qkv  = (const float*)d_in[1];
    const float* b_qkv  = (const float*)d_in[2];
    const float* rel_pos= (const float*)d_in[3];
    const float* gn_w   = (const float*)d_in[4];
    const float* gn_b   = (const float*)d_in[5];
    const float* sq1    = (const float*)d_in[6];
    const float* sq2    = (const float*)d_in[7];
    const float* gwc    = (const float*)d_in[8];
    const float* gwc_b  = (const float*)d_in[9];
    const float* pwc1   = (const float*)d_in[10];
    const float* pwc2   = (const float*)d_in[11];
    const float* w_out  = (const float*)d_in[12];
    const float* b_out  = (const float*)d_in[13];
    float* out = (float*)d_out;

    float *p_wqkv, *p_wout, *p_wpwc2, *p_wsq, *p_wgwcp;
    cudaGetSymbolAddress((void**)&p_wqkv,  g_wqkv_t);
    cudaGetSymbolAddress((void**)&p_wout,  g_wout_t);
    cudaGetSymbolAddress((void**)&p_wpwc2, g_wpwc2_t);
    cudaGetSymbolAddress((void**)&p_wsq,   g_wsq_t);
    cudaGetSymbolAddress((void**)&p_wgwcp, g_wgwcp_t);

    zero_small<<<4, 256>>>();
    transpose_w<<<(768*256 + 255)/256, 256>>>(w_qkv, p_wqkv, 768, 256);
    transpose_w<<<(256*256 + 255)/256, 256>>>(w_out, p_wout, 256, 256);
    transpose_w<<<(192*64 + 255)/256, 256>>>(pwc2, p_wpwc2, 192, 64);
    make_sq<<<128, 256>>>(sq1, sq2);
    make_gwcp<<<(2*352*128 + 255)/256, 256>>>(gwc, pwc1);
    sum_gnw<<<1, 256>>>(gn_w);

    sgemm_k<<<dim3(6, 1024, 1), 256>>>(AQKV{x}, p_wqkv, 0, EQKV{b_qkv}, 768, 256);

    gn_stats<<<256, 256>>>();
    sru_elem<<<65536, 256>>>(gn_w, gn_b);

    sgemm_k<<<dim3(1, 1024, 1), 256>>>(AKtok{}, p_wsq, 0, EUL{}, 128, 256);
    sgemm_k<<<dim3(1, 1024, 2), 256>>>(AConvP{}, p_wgwcp, 352*128, EY1{gwc_b}, 128, 352);
    sgemm_k<<<dim3(2, 1024, 1), 256>>>(ALow{}, p_wpwc2, 0, EY2{}, 192, 64);
    softmax512<<<2, 512>>>(gwc_b);
    cru_combine<<<131072, 256>>>();

    attn<<<dim3(1024, 8, 2), 64>>>(rel_pos);
    sgemm_out<<<dim3(2, 1024), 256>>>(p_wout, b_out, out);
}

// round 6
// speedup vs baseline: 1.2311x; 1.2311x over previous
#include <cuda_runtime.h>
#include <cuda_bf16.h>
#include <math.h>
#include <cstdint>

#define TTOT 131072
#define SCALE 0.17677669529663687f
#define GN_N 1048576.0f

typedef unsigned long long ull;

__device__ __forceinline__ ull pack2(float a, float b) {
    ull r; asm("mov.b64 %0, {%1, %2};" : "=l"(r) : "f"(a), "f"(b)); return r;
}
__device__ __forceinline__ void unpack2(ull p, float& a, float& b) {
    asm("mov.b64 {%0, %1}, %2;" : "=f"(a), "=f"(b) : "l"(p));
}
__device__ __forceinline__ void ffma2(ull& d, ull a, ull b) {
    asm("fma.rn.f32x2 %0, %1, %2, %0;" : "+l"(d) : "l"(a), "l"(b));
}
__device__ __forceinline__ void mma16816(float* d, const uint32_t* a, const uint32_t* b) {
    asm volatile("mma.sync.aligned.m16n8k16.row.col.f32.bf16.bf16.f32 "
        "{%0,%1,%2,%3}, {%4,%5,%6,%7}, {%8,%9}, {%0,%1,%2,%3};"
        : "+f"(d[0]), "+f"(d[1]), "+f"(d[2]), "+f"(d[3])
        : "r"(a[0]), "r"(a[1]), "r"(a[2]), "r"(a[3]), "r"(b[0]), "r"(b[1]));
}

// ---------------- scratch ----------------
__device__ __nv_bfloat16 g_xs  [(size_t)TTOT*768];  // [hi|lo|hi] split x
__device__ __nv_bfloat16 g_atts[(size_t)TTOT*768];  // split attention out
__device__ float g_q  [(size_t)TTOT*256];
__device__ float g_k  [(size_t)TTOT*256];
__device__ float g_v  [(size_t)TTOT*256];
__device__ float g_qa [(size_t)TTOT*256];
__device__ float g_ka [(size_t)TTOT*256];
__device__ float g_ul [(size_t)TTOT*128];
__device__ float g_y1 [(size_t)TTOT*256];
__device__ float g_y2 [(size_t)TTOT*192];
__device__ __nv_bfloat16 g_bq  [768*768];
__device__ __nv_bfloat16 g_bout[256*768];
__device__ float g_wsq_t  [256*128];
__device__ float g_wgwcp_t[2*352*128];
__device__ float g_wpwc2_t[64*192];
__device__ float g_gnstats[2*16*2];
__device__ float g_pool[2*512];
__device__ float g_misc[4];

// ---------------- small utilities ----------------
__global__ void zero_small() {
    int i = blockIdx.x*256 + threadIdx.x;
    if (i < 1024) g_pool[i] = 0.f;
    if (i < 64)   g_gnstats[i] = 0.f;
}
__global__ void transpose_w(const float* __restrict__ in, float* __restrict__ out, int N, int K) {
    int i = blockIdx.x*256 + threadIdx.x;
    if (i >= N*K) return;
    out[i] = in[(i % N)*K + (i / N)];
}
__global__ void make_sq(const float* __restrict__ sq1, const float* __restrict__ sq2) {
    int i = blockIdx.x*256 + threadIdx.x;
    if (i >= 256*128) return;
    int n = i & 127, k = i >> 7;
    float v = 0.f;
    if (n < 64)  { if (k < 128)  v = sq1[n*128 + k]; }
    else         { if (k >= 128) v = sq2[(n-64)*128 + (k-128)]; }
    g_wsq_t[i] = v;
}
__global__ void make_gwcp(const float* __restrict__ gwc, const float* __restrict__ pwc1) {
    int i = blockIdx.x*256 + threadIdx.x;
    if (i >= 2*352*128) return;
    int z = i / 45056, r = i % 45056;
    int k = r >> 7, n = r & 127;
    int c = z*128 + n;
    g_wgwcp_t[i] = (k < 288) ? gwc[c*288 + k] : pwc1[c*64 + (k - 288)];
}
__global__ void sum_gnw(const float* __restrict__ gn_w) {
    __shared__ float sh[256];
    sh[threadIdx.x] = gn_w[threadIdx.x];
    __syncthreads();
    for (int st = 128; st > 0; st >>= 1) {
        if (threadIdx.x < st) sh[threadIdx.x] += sh[threadIdx.x + st];
        __syncthreads();
    }
    if (threadIdx.x == 0) g_misc[0] = sh[0];
}
// split weight prep: B'[n][kp], kp = [hi|hi|lo]
__global__ void prep_bw(const float* __restrict__ w, __nv_bfloat16* __restrict__ dst, int N) {
    int i = blockIdx.x*256 + threadIdx.x;
    if (i >= N*768) return;
    int n = i / 768, kp = i % 768;
    int seg = kp >> 8, kk = kp & 255;
    float v = w[n*256 + kk];
    __nv_bfloat16 h = __float2bfloat16(v);
    dst[i] = (seg == 2) ? __float2bfloat16(v - __bfloat162float(h)) : h;
}

// ---------------- roll + split x -> token-major [t][768] bf16 ----------------
__global__ __launch_bounds__(256) void xsplit(const float* __restrict__ x) {
    __shared__ float s[256][33];
    int bid = blockIdx.x;
    int b = bid >> 11, rem = bid & 2047;
    int hr = rem >> 3, w0 = (rem & 7) << 5;
    int tid = threadIdx.x, wid = tid >> 5, lane = tid & 31;
    int hs = ((hr + 4) & 255) << 8;
    for (int i = 0; i < 32; i++) {
        int idx = (i << 8) + tid;
        int c = idx >> 5, wp = idx & 31;
        s[c][wp] = x[(size_t)((b << 8) + c)*65536 + hs + ((w0 + wp + 4) & 255)];
    }
    __syncthreads();
    size_t t = (size_t)(b << 16) + (hr << 8) + w0 + lane;
    int c0 = wid << 5;
    __nv_bfloat16* dst = &g_xs[t*768];
    for (int j = 0; j < 32; j += 8) {
        __nv_bfloat16 hv[8], lv[8];
#pragma unroll
        for (int e = 0; e < 8; e++) {
            float a = s[c0 + j + e][lane];
            hv[e] = __float2bfloat16(a);
            lv[e] = __float2bfloat16(a - __bfloat162float(hv[e]));
        }
        *(uint4*)&dst[c0 + j]       = *(uint4*)hv;
        *(uint4*)&dst[256 + c0 + j] = *(uint4*)lv;
        *(uint4*)&dst[512 + c0 + j] = *(uint4*)hv;
    }
}

// ---------------- HMMA GEMM: 128x128 tile, K'=768, mma.sync bf16 ----------------
struct EQKVt {
    const float* bias;
    __device__ void st2(int m, int n, float v0, float v1) const {
        float* dst;
        if (n < 256)      dst = &g_q[(size_t)m*256 + n];
        else if (n < 512) dst = &g_k[(size_t)m*256 + n - 256];
        else              dst = &g_v[(size_t)m*256 + n - 512];
        *(float2*)dst = make_float2(v0 + bias[n], v1 + bias[n+1]);
    }
};
struct EOutT {
    const float* bias;
    __device__ void st2(int m, int n, float v0, float v1) const {
        *(float2*)&g_qa[(size_t)m*256 + n] = make_float2(v0 + bias[n], v1 + bias[n+1]);
    }
};
template<class EF>
__global__ __launch_bounds__(256, 2) void hgemm(const __nv_bfloat16* __restrict__ A,
                                                const __nv_bfloat16* __restrict__ B, EF ef) {
    // padded fragment-friendly layout: 4 k16-groups x [128 rows][24 bf16]
    __shared__ __align__(16) __nv_bfloat16 As[4][128][24];
    __shared__ __align__(16) __nv_bfloat16 Bs[4][128][24];
    int tid = threadIdx.x, lane = tid & 31, wid = tid >> 5;
    int m0 = blockIdx.y << 7, n0 = blockIdx.x << 7;
    int wm = (wid & 3) << 5;      // warp M offset (32-row tile)
    int wn = (wid >> 2) << 6;     // warp N offset (64-col tile)
    int gid = lane >> 2, tig = lane & 3;
    float acc[2][8][4];
#pragma unroll
    for (int mf = 0; mf < 2; mf++)
#pragma unroll
        for (int nf = 0; nf < 8; nf++)
#pragma unroll
            for (int e = 0; e < 4; e++) acc[mf][nf][e] = 0.f;

    for (int ch = 0; ch < 12; ch++) {
        int k0 = ch << 6;
#pragma unroll
        for (int i = 0; i < 4; i++) {
            int idx = (i << 8) + tid;
            int r = idx >> 3, c8 = idx & 7;
            *(uint4*)&As[c8 >> 1][r][(c8 & 1) << 3] =
                *(const uint4*)(A + (size_t)(m0 + r)*768 + k0 + (c8 << 3));
            *(uint4*)&Bs[c8 >> 1][r][(c8 & 1) << 3] =
                *(const uint4*)(B + (size_t)(n0 + r)*768 + k0 + (c8 << 3));
        }
        __syncthreads();
#pragma unroll
        for (int g = 0; g < 4; g++) {
            uint32_t a[2][4], b[8][2];
#pragma unroll
            for (int mf = 0; mf < 2; mf++) {
                const __nv_bfloat16* base = &As[g][wm + (mf << 4) + gid][tig << 1];
                a[mf][0] = *(const uint32_t*)base;
                a[mf][1] = *(const uint32_t*)(base + 8*24);
                a[mf][2] = *(const uint32_t*)(base + 8);
                a[mf][3] = *(const uint32_t*)(base + 8*24 + 8);
            }
#pragma unroll
            for (int nf = 0; nf < 8; nf++) {
                const __nv_bfloat16* base = &Bs[g][wn + (nf << 3) + gid][tig << 1];
                b[nf][0] = *(const uint32_t*)base;
                b[nf][1] = *(const uint32_t*)(base + 8);
            }
#pragma unroll
            for (int mf = 0; mf < 2; mf++)
#pragma unroll
                for (int nf = 0; nf < 8; nf++)
                    mma16816(acc[mf][nf], a[mf], b[nf]);
        }
        __syncthreads();
    }
#pragma unroll
    for (int mf = 0; mf < 2; mf++) {
        int row0 = m0 + wm + (mf << 4) + gid;
#pragma unroll
        for (int nf = 0; nf < 8; nf++) {
            int col = n0 + wn + (nf << 3) + (tig << 1);
            ef.st2(row0,     col, acc[mf][nf][0], acc[mf][nf][1]);
            ef.st2(row0 + 8, col, acc[mf][nf][2], acc[mf][nf][3]);
        }
    }
}

// ---------------- FFMA2 SGEMM (CRU path) ----------------
template<class AF, class EF>
__global__ __launch_bounds__(256, 2) void sgemm_k(AF af, const float* __restrict__ Bt,
                                                  int bstride, EF ef, int N, int K) {
    __shared__ __align__(16) float As[16][128];
    __shared__ __align__(16) float Bs[16][128];
    int z = blockIdx.z;
    const float* B = Bt + (size_t)z * bstride;
    int m0 = blockIdx.y << 7, n0 = blockIdx.x << 7;
    int tid = threadIdx.x;
    int r0 = (tid >> 4) << 3, c0 = (tid & 15) << 3;
    ull acc2[8][4];
    ull zz = pack2(0.f, 0.f);
#pragma unroll
    for (int i = 0; i < 8; i++)
#pragma unroll
        for (int j = 0; j < 4; j++) acc2[i][j] = zz;
    for (int k0 = 0; k0 < K; k0 += 16) {
#pragma unroll
        for (int i = 0; i < 8; i++) {
            int idx = (i << 8) + tid;
            As[idx >> 7][idx & 127] = af(m0 + (idx & 127), k0 + (idx >> 7), z);
        }
#pragma unroll
        for (int i = 0; i < 8; i++) {
            int idx = (i << 8) + tid;
            int cc = idx & 127, kk = idx >> 7;
            int n = n0 + cc;
            Bs[kk][cc] = (n < N) ? B[(size_t)(k0 + kk)*N + n] : 0.f;
        }
        __syncthreads();
#pragma unroll
        for (int kk = 0; kk < 16; kk++) {
            float4 a0 = *(const float4*)&As[kk][r0];
            float4 a1 = *(const float4*)&As[kk][r0 + 4];
            const ull* bp = (const ull*)&Bs[kk][c0];
            ull b0 = bp[0], b1 = bp[1], b2 = bp[2], b3 = bp[3];
            float av[8] = {a0.x, a0.y, a0.z, a0.w, a1.x, a1.y, a1.z, a1.w};
#pragma unroll
            for (int i = 0; i < 8; i++) {
                ull ai = pack2(av[i], av[i]);
                ffma2(acc2[i][0], ai, b0); ffma2(acc2[i][1], ai, b1);
                ffma2(acc2[i][2], ai, b2); ffma2(acc2[i][3], ai, b3);
            }
        }
        __syncthreads();
    }
    float psum[8];
#pragma unroll
    for (int j = 0; j < 8; j++) psum[j] = 0.f;
#pragma unroll
    for (int i = 0; i < 8; i++) {
        int m = m0 + r0 + i;
#pragma unroll
        for (int j = 0; j < 4; j++) {
            float lo, hi;
            unpack2(acc2[i][j], lo, hi);
            int n = n0 + c0 + 2*j;
            if (n < N)     ef(m, n,     z, lo);
            if (n + 1 < N) ef(m, n + 1, z, hi);
            psum[2*j] += lo; psum[2*j+1] += hi;
        }
    }
    float* red = &As[0][0];
    __syncthreads();
#pragma unroll
    for (int j = 0; j < 8; j++) red[(tid >> 4)*128 + c0 + j] = psum[j];
    __syncthreads();
    if (tid < 128) {
        int n = n0 + tid;
        float s = 0.f;
#pragma unroll
        for (int r = 0; r < 16; r++) s += red[r*128 + tid];
        if (n < N) {
            int slot = ef.pslot(n, z, m0 >> 16);
            if (slot >= 0) atomicAdd(&g_pool[slot], s);
        }
    }
}
struct AKtok {
    __device__ float operator()(int t, int k, int z) const { return g_k[(size_t)t*256 + k]; }
};
struct ALow {
    __device__ float operator()(int t, int k, int z) const { return g_ul[(size_t)t*128 + 64 + k]; }
};
struct AConvP {
    __device__ float operator()(int t, int k, int z) const {
        if (k >= 288) return g_ul[(size_t)t*128 + (k - 288)];
        int kl = k / 9, tap = k - kl*9;
        int kin = (z << 5) + kl;
        int dy = tap/3 - 1, dx = tap - (tap/3)*3 - 1;
        int b = t >> 16, pixi = t & 65535;
        int hr = (pixi >> 8) + dy, wr = (pixi & 255) + dx;
        if ((unsigned)hr > 255u || (unsigned)wr > 255u) return 0.f;
        return g_ul[(size_t)((b << 16) + (hr << 8) + wr)*128 + kin];
    }
};
struct EUL {
    __device__ void operator()(int t, int n, int z, float v) const { g_ul[(size_t)t*128 + n] = v; }
    __device__ int pslot(int n, int z, int b) const { return n >= 64 ? (b << 9) + 448 + (n - 64) : -1; }
};
struct EY1 {
    const float* bias;
    __device__ void operator()(int t, int n, int z, float v) const {
        int c = (z << 7) + n;
        g_y1[(size_t)t*256 + c] = v + bias[c];
    }
    __device__ int pslot(int n, int z, int b) const { return (b << 9) + (z << 7) + n; }
};
struct EY2 {
    __device__ void operator()(int t, int n, int z, float v) const { g_y2[(size_t)t*192 + n] = v; }
    __device__ int pslot(int n, int z, int b) const { return (b << 9) + 256 + n; }
};

// ---------------- GN stats / SRU / CRU glue ----------------
__global__ void gn_stats() {
    int t0 = blockIdx.x * 512;
    int c = threadIdx.x;
    const float* p = g_q + (size_t)t0*256 + c;
    float s = 0.f, s2 = 0.f;
#pragma unroll 4
    for (int i = 0; i < 512; i++) { float v = p[(size_t)i*256]; s += v; s2 += v*v; }
#pragma unroll
    for (int off = 8; off > 0; off >>= 1) {
        s  += __shfl_down_sync(0xffffffff, s,  off, 16);
        s2 += __shfl_down_sync(0xffffffff, s2, off, 16);
    }
    if ((c & 15) == 0) {
        int b = t0 >> 16, g = c >> 4;
        atomicAdd(&g_gnstats[((b << 4) + g)*2],     s);
        atomicAdd(&g_gnstats[((b << 4) + g)*2 + 1], s2);
    }
}
__global__ void sru_elem(const float* __restrict__ gn_w, const float* __restrict__ gn_b) {
    int i = blockIdx.x*256 + threadIdx.x;
    int t = i >> 7, cp = i & 127;
    int b = t >> 16;
    int c1 = cp, c2 = cp + 128;
    float wsum = g_misc[0];
    int g1 = c1 >> 4, g2 = c2 >> 4;
    float m1 = g_gnstats[((b<<4)+g1)*2] / GN_N;
    float v1 = g_gnstats[((b<<4)+g1)*2+1] / GN_N - m1*m1;
    float m2 = g_gnstats[((b<<4)+g2)*2] / GN_N;
    float v2 = g_gnstats[((b<<4)+g2)*2+1] / GN_N - m2*m2;
    float w1c = gn_w[c1], w2c = gn_w[c2];
    float A1 = rsqrtf(v1 + 1e-5f)*w1c, B1 = gn_b[c1] - m1*rsqrtf(v1 + 1e-5f)*w1c;
    float A2 = rsqrtf(v2 + 1e-5f)*w2c, B2 = gn_b[c2] - m2*rsqrtf(v2 + 1e-5f)*w2c;
    float x1 = g_q[(size_t)t*256 + c1], x2 = g_q[(size_t)t*256 + c2];
    float rw1 = 1.0f/(1.0f + expf(-(x1*A1 + B1)*(w1c/wsum)));
    float rw2 = 1.0f/(1.0f + expf(-(x2*A2 + B2)*(w2c/wsum)));
    float w11 = rw1 > 0.5f ? 1.0f : rw1, w21 = rw1 > 0.5f ? 0.0f : rw1;
    float w12 = rw2 > 0.5f ? 1.0f : rw2, w22 = rw2 > 0.5f ? 0.0f : rw2;
    g_qa[(size_t)t*256 + c1] = w11*x1 + w22*x2;
    g_qa[(size_t)t*256 + c2] = w12*x2 + w21*x1;
}
__global__ void softmax512(const float* __restrict__ gwc_b) {
    int b = blockIdx.x, t = threadIdx.x;
    __shared__ float sh[512];
    float v = g_pool[(b << 9) + t] * (1.0f/65536.0f);
    if (t < 256) v += gwc_b[t];
    sh[t] = v;
    __syncthreads();
    for (int st = 256; st > 0; st >>= 1) { if (t < st) sh[t] = fmaxf(sh[t], sh[t + st]); __syncthreads(); }
    float mx = sh[0];
    __syncthreads();
    float e = expf(v - mx);
    sh[t] = e;
    __syncthreads();
    for (int st = 256; st > 0; st >>= 1) { if (t < st) sh[t] += sh[t + st]; __syncthreads(); }
    float sum = sh[0];
    __syncthreads();
    g_pool[(b << 9) + t] = e / sum;
}
__global__ void cru_combine() {
    int i = blockIdx.x*256 + threadIdx.x;
    int t = i >> 8, c = i & 255;
    int b = t >> 16;
    float y1 = g_y1[i];
    float y2v = (c < 192) ? g_y2[(size_t)t*192 + c] : g_ul[(size_t)t*128 + 64 + (c - 192)];
    g_ka[(size_t)t*256 + c] = g_pool[(b << 9) + c]*y1 + g_pool[(b << 9) + 256 + c]*y2v;
}

// ---------------- windowed attention (split-bf16 output) ----------------
__global__ __launch_bounds__(64) void attn(const float* __restrict__ rel_pos) {
    int win = blockIdx.x, h = blockIdx.y, b = blockIdx.z;
    __shared__ __align__(16) float ksh[2048];
    __shared__ __align__(16) float vsh[2048];
    __shared__ float rp[225];
    int wy = win >> 5, wx = win & 31;
    int t0 = (b << 16) + (wy << 11) + (wx << 3);
    int tid = threadIdx.x;
    int hb = h << 5;
    for (int i = tid; i < 2048; i += 64) {
        int p = i >> 5, d = i & 31;
        int t = t0 + ((p >> 3) << 8) + (p & 7);
        ksh[i] = g_ka[(size_t)t*256 + hb + d];
        vsh[i] = g_v [(size_t)t*256 + hb + d];
    }
    for (int i = tid; i < 225; i += 64) rp[i] = rel_pos[h*225 + i];
    __syncthreads();
    int myt = t0 + ((tid >> 3) << 8) + (tid & 7);
    ull qp[16];
#pragma unroll
    for (int d = 0; d < 16; d++) {
        float2 qv = *(const float2*)&g_qa[(size_t)myt*256 + hb + 2*d];
        qp[d] = pack2(qv.x, qv.y);
    }
    int ph = tid >> 3, pw = tid & 7;
    bool lr = wy == 31, lc = wx == 31;
    ull zz = pack2(0.f, 0.f);
    float s[64];
#pragma unroll
    for (int qi = 0; qi < 64; qi++) {
        const ull* kp = (const ull*)&ksh[qi*32];
        ull dp = zz;
#pragma unroll
        for (int d = 0; d < 16; d++) ffma2(dp, qp[d], kp[d]);
        float dl, dh;
        unpack2(dp, dl, dh);
        int qh = qi >> 3, qw = qi & 7;
        float val = (dl + dh)*SCALE + rp[(ph - qh + 7)*15 + (pw - qw + 7)];
        if ((lr && ((ph < 4) != (qh < 4))) || (lc && ((pw < 4) != (qw < 4)))) val = -1e30f;
        s[qi] = val;
    }
    float mx = -1e30f;
#pragma unroll
    for (int qi = 0; qi < 64; qi++) mx = fmaxf(mx, s[qi]);
    float sum = 0.f;
#pragma unroll
    for (int qi = 0; qi < 64; qi++) { s[qi] = expf(s[qi] - mx); sum += s[qi]; }
    float inv = 1.0f / sum;
    ull accp[16];
#pragma unroll
    for (int d = 0; d < 16; d++) accp[d] = zz;
#pragma unroll
    for (int qi = 0; qi < 64; qi++) {
        ull wd = pack2(s[qi]*inv, s[qi]*inv);
        const ull* vp = (const ull*)&vsh[qi*32];
#pragma unroll
        for (int d = 0; d < 16; d++) ffma2(accp[d], wd, vp[d]);
    }
    float af[32];
#pragma unroll
    for (int d = 0; d < 16; d++) unpack2(accp[d], af[2*d], af[2*d+1]);
    __nv_bfloat16* dst = &g_atts[(size_t)myt*768];
#pragma unroll
    for (int d0 = 0; d0 < 32; d0 += 8) {
        __nv_bfloat16 hv[8], lv[8];
#pragma unroll
        for (int e = 0; e < 8; e++) {
            hv[e] = __float2bfloat16(af[d0 + e]);
            lv[e] = __float2bfloat16(af[d0 + e] - __bfloat162float(hv[e]));
        }
        *(uint4*)&dst[hb + d0]       = *(uint4*)hv;
        *(uint4*)&dst[256 + hb + d0] = *(uint4*)lv;
        *(uint4*)&dst[512 + hb + d0] = *(uint4*)hv;
    }
}

// ---------------- final un-roll scatter to NCHW ----------------
__global__ __launch_bounds__(256) void unscatter(float* __restrict__ out) {
    __shared__ float s2[32][261];
    int bid = blockIdx.x;
    int b = bid >> 11, rem = bid & 2047;
    int hr = rem >> 3, w0 = (rem & 7) << 5;
    int tid = threadIdx.x;
    size_t tbase = (size_t)(b << 16) + (hr << 8) + w0;
    for (int i = 0; i < 8; i++) {
        int idx = (i << 8) + tid;
        int tw = idx >> 6, c4 = idx & 63;
        float4 v = *(const float4*)&g_qa[(tbase + tw)*256 + (c4 << 2)];
        s2[tw][(c4 << 2)]     = v.x;
        s2[tw][(c4 << 2) + 1] = v.y;
        s2[tw][(c4 << 2) + 2] = v.z;
        s2[tw][(c4 << 2) + 3] = v.w;
    }
    __syncthreads();
    int hs = ((hr + 4) & 255) << 8;
    for (int i = 0; i < 32; i++) {
        int idx = (i << 8) + tid;
        int c = idx >> 5, wp = idx & 31;
        out[(size_t)((b << 8) + c)*65536 + hs + ((w0 + wp + 4) & 255)] = s2[wp][c];
    }
}

// ---------------- launch ----------------
extern "C" void kernel_launch(void* const* d_in, const int* in_sizes, int n_in,
                              void* d_out, int out_size) {
    const float* x      = (const float*)d_in[0];
    const float* w_qkv  = (const float*)d_in[1];
    const float* b_qkv  = (const float*)d_in[2];
    const float* rel_pos= (const float*)d_in[3];
    const float* gn_w   = (const float*)d_in[4];
    const float* gn_b   = (const float*)d_in[5];
    const float* sq1    = (const float*)d_in[6];
    const float* sq2    = (const float*)d_in[7];
    const float* gwc    = (const float*)d_in[8];
    const float* gwc_b  = (const float*)d_in[9];
    const float* pwc1   = (const float*)d_in[10];
    const float* pwc2   = (const float*)d_in[11];
    const float* w_out  = (const float*)d_in[12];
    const float* b_out  = (const float*)d_in[13];
    float* out = (float*)d_out;

    __nv_bfloat16 *p_bq, *p_bout, *p_xs, *p_atts;
    float *p_wpwc2, *p_wsq, *p_wgwcp;
    cudaGetSymbolAddress((void**)&p_bq,    g_bq);
    cudaGetSymbolAddress((void**)&p_bout,  g_bout);
    cudaGetSymbolAddress((void**)&p_xs,    g_xs);
    cudaGetSymbolAddress((void**)&p_atts,  g_atts);
    cudaGetSymbolAddress((void**)&p_wpwc2, g_wpwc2_t);
    cudaGetSymbolAddress((void**)&p_wsq,   g_wsq_t);
    cudaGetSymbolAddress((void**)&p_wgwcp, g_wgwcp_t);

    zero_small<<<4, 256>>>();
    prep_bw<<<(768*768 + 255)/256, 256>>>(w_qkv, p_bq, 768);
    prep_bw<<<(256*768 + 255)/256, 256>>>(w_out, p_bout, 256);
    transpose_w<<<(192*64 + 255)/256, 256>>>(pwc2, p_wpwc2, 192, 64);
    make_sq<<<128, 256>>>(sq1, sq2);
    make_gwcp<<<(2*352*128 + 255)/256, 256>>>(gwc, pwc1);
    sum_gnw<<<1, 256>>>(gn_w);

    xsplit<<<4096, 256>>>(x);
    hgemm<EQKVt><<<dim3(6, 1024), 256>>>(p_xs, p_bq, EQKVt{b_qkv});

    gn_stats<<<256, 256>>>();
    sru_elem<<<65536, 256>>>(gn_w, gn_b);

    sgemm_k<<<dim3(1, 1024, 1), 256>>>(AKtok{}, p_wsq, 0, EUL{}, 128, 256);
    sgemm_k<<<dim3(1, 1024, 2), 256>>>(AConvP{}, p_wgwcp, 352*128, EY1{gwc_b}, 128, 352);
    sgemm_k<<<dim3(2, 1024, 1), 256>>>(ALow{}, p_wpwc2, 0, EY2{}, 192, 64);
    softmax512<<<2, 512>>>(gwc_b);
    cru_combine<<<131072, 256>>>();

    attn<<<dim3(1024, 8, 2), 64>>>(rel_pos);
    hgemm<EOutT><<<dim3(2, 1024), 256>>>(p_atts, p_bout, EOutT{b_out});
    unscatter<<<4096, 256>>>(out);
}

// round 7
// speedup vs baseline: 1.5497x; 1.2588x over previous
#include <cuda_runtime.h>
#include <cuda_bf16.h>
#include <math.h>
#include <cstdint>

#define TTOT 131072
#define SCALE 0.17677669529663687f
#define GN_N 1048576.0f

typedef unsigned long long ull;

__device__ __forceinline__ ull pack2(float a, float b) {
    ull r; asm("mov.b64 %0, {%1, %2};" : "=l"(r) : "f"(a), "f"(b)); return r;
}
__device__ __forceinline__ void unpack2(ull p, float& a, float& b) {
    asm("mov.b64 {%0, %1}, %2;" : "=f"(a), "=f"(b) : "l"(p));
}
__device__ __forceinline__ void ffma2(ull& d, ull a, ull b) {
    asm("fma.rn.f32x2 %0, %1, %2, %0;" : "+l"(d) : "l"(a), "l"(b));
}
__device__ __forceinline__ void mma16816(float* d, const uint32_t* a, const uint32_t* b) {
    asm volatile("mma.sync.aligned.m16n8k16.row.col.f32.bf16.bf16.f32 "
        "{%0,%1,%2,%3}, {%4,%5,%6,%7}, {%8,%9}, {%0,%1,%2,%3};"
        : "+f"(d[0]), "+f"(d[1]), "+f"(d[2]), "+f"(d[3])
        : "r"(a[0]), "r"(a[1]), "r"(a[2]), "r"(a[3]), "r"(b[0]), "r"(b[1]));
}
__device__ __forceinline__ uint32_t smem_u32(const void* p) {
    uint32_t a;
    asm("{ .reg .u64 t; cvta.to.shared.u64 t, %1; cvt.u32.u64 %0, t; }" : "=r"(a) : "l"(p));
    return a;
}
__device__ __forceinline__ float bf2f(__nv_bfloat16 h) { return __bfloat162float(h); }

#define CP_A16(d, s) asm volatile("cp.async.cg.shared.global [%0], [%1], 16;" :: "r"(d), "l"(s) : "memory")
#define CP_COMMIT()  asm volatile("cp.async.commit_group;" ::: "memory")
#define CP_WAIT1()   asm volatile("cp.async.wait_group 1;" ::: "memory")

// ---------------- scratch ----------------
__device__ __nv_bfloat16 g_xs  [(size_t)TTOT*768];  // [hi|lo|hi] split x
__device__ __nv_bfloat16 g_ks  [(size_t)TTOT*768];  // split k
__device__ __nv_bfloat16 g_atts[(size_t)TTOT*768];  // split attention out
__device__ __nv_bfloat16 g_uphi[(size_t)TTOT*64];
__device__ __nv_bfloat16 g_uplo[(size_t)TTOT*64];
__device__ __nv_bfloat16 g_uls2[(size_t)TTOT*192];  // low split [hi|lo|hi]
__device__ float g_q  [(size_t)TTOT*256];
__device__ float g_v  [(size_t)TTOT*256];
__device__ float g_qa [(size_t)TTOT*256];
__device__ float g_ka [(size_t)TTOT*256];
__device__ float g_y1 [(size_t)TTOT*256];
__device__ float g_y2 [(size_t)TTOT*192];
__device__ __nv_bfloat16 g_bq    [768*768];
__device__ __nv_bfloat16 g_bout  [256*768];
__device__ __nv_bfloat16 g_bsq   [128*768];
__device__ __nv_bfloat16 g_bconv2[2*128*1088];
__device__ __nv_bfloat16 g_bpwc2n[256*192];
__device__ float g_gnstats[2*16*2];
__device__ float g_pool[2*512];
__device__ float g_misc[4];

// ---------------- small utilities ----------------
__global__ void zero_small() {
    int i = blockIdx.x*256 + threadIdx.x;
    if (i < 1024) g_pool[i] = 0.f;
    if (i < 64)   g_gnstats[i] = 0.f;
}
__global__ void sum_gnw(const float* __restrict__ gn_w) {
    __shared__ float sh[256];
    sh[threadIdx.x] = gn_w[threadIdx.x];
    __syncthreads();
    for (int st = 128; st > 0; st >>= 1) {
        if (threadIdx.x < st) sh[threadIdx.x] += sh[threadIdx.x + st];
        __syncthreads();
    }
    if (threadIdx.x == 0) g_misc[0] = sh[0];
}
__global__ void prep_bw(const float* __restrict__ w, __nv_bfloat16* __restrict__ dst, int N) {
    int i = blockIdx.x*256 + threadIdx.x;
    if (i >= N*768) return;
    int n = i / 768, kp = i % 768;
    int seg = kp >> 8, kk = kp & 255;
    float v = w[n*256 + kk];
    __nv_bfloat16 h = __float2bfloat16(v);
    dst[i] = (seg == 2) ? __float2bfloat16(v - bf2f(h)) : h;
}
__global__ void prep_bsq(const float* __restrict__ sq1, const float* __restrict__ sq2) {
    int i = blockIdx.x*256 + threadIdx.x;
    if (i >= 128*768) return;
    int n = i / 768, kp = i % 768;
    int seg = kp >> 8, kk = kp & 255;
    float w = 0.f;
    if (n < 64)  { if (kk < 128)  w = sq1[n*128 + kk]; }
    else         { if (kk >= 128) w = sq2[(n-64)*128 + (kk-128)]; }
    __nv_bfloat16 h = __float2bfloat16(w);
    g_bsq[i] = (seg == 2) ? __float2bfloat16(w - bf2f(h)) : h;
}
__global__ void prep_bconv2(const float* __restrict__ gwc, const float* __restrict__ pwc1) {
    int i = blockIdx.x*256 + threadIdx.x;
    if (i >= 2*128*1088) return;
    int z = i / (128*1088), r = i % (128*1088);
    int n = r / 1088, kp = r % 1088;
    float w = 0.f; int seg = 0;
    if (kp < 1056) {
        seg = kp / 352;
        int kk = kp - seg*352;
        int c = z*128 + n;
        if (kk < 288) { int tap = kk >> 5, kl = kk & 31; w = gwc[c*288 + kl*9 + tap]; }
        else          w = pwc1[c*64 + kk - 288];
    }
    __nv_bfloat16 h = __float2bfloat16(w);
    g_bconv2[i] = (seg == 2) ? __float2bfloat16(w - bf2f(h)) : h;
}
__global__ void prep_bpwc2n(const float* __restrict__ pwc2) {
    int i = blockIdx.x*256 + threadIdx.x;
    if (i >= 256*192) return;
    int n = i / 192, kp = i % 192;
    int seg = kp >> 6, kk = kp & 63;
    float w = (n < 192) ? pwc2[n*64 + kk] : 0.f;
    __nv_bfloat16 h = __float2bfloat16(w);
    g_bpwc2n[i] = (seg == 2) ? __float2bfloat16(w - bf2f(h)) : h;
}

// ---------------- roll + split x ----------------
__global__ __launch_bounds__(256) void xsplit(const float* __restrict__ x) {
    __shared__ float s[256][33];
    int bid = blockIdx.x;
    int b = bid >> 11, rem = bid & 2047;
    int hr = rem >> 3, w0 = (rem & 7) << 5;
    int tid = threadIdx.x, wid = tid >> 5, lane = tid & 31;
    int hs = ((hr + 4) & 255) << 8;
    for (int i = 0; i < 32; i++) {
        int idx = (i << 8) + tid;
        int c = idx >> 5, wp = idx & 31;
        s[c][wp] = x[(size_t)((b << 8) + c)*65536 + hs + ((w0 + wp + 4) & 255)];
    }
    __syncthreads();
    size_t t = (size_t)(b << 16) + (hr << 8) + w0 + lane;
    int c0 = wid << 5;
    __nv_bfloat16* dst = &g_xs[t*768];
    for (int j = 0; j < 32; j += 8) {
        __nv_bfloat16 hv[8], lv[8];
#pragma unroll
        for (int e = 0; e < 8; e++) {
            float a = s[c0 + j + e][lane];
            hv[e] = __float2bfloat16(a);
            lv[e] = __float2bfloat16(a - bf2f(hv[e]));
        }
        *(uint4*)&dst[c0 + j]       = *(uint4*)hv;
        *(uint4*)&dst[256 + c0 + j] = *(uint4*)lv;
        *(uint4*)&dst[512 + c0 + j] = *(uint4*)hv;
    }
}

// ---------------- epilogues ----------------
struct EQKVt {
    const float* bias;
    __device__ void st2(int m, int n, int z, float v0, float v1) const {
        v0 += bias[n]; v1 += bias[n+1];
        if (n < 256) {
            *(float2*)&g_q[(size_t)m*256 + n] = make_float2(v0, v1);
        } else if (n < 512) {
            int c = n - 256;
            __nv_bfloat16 h0 = __float2bfloat16(v0), h1 = __float2bfloat16(v1);
            __nv_bfloat162 hh = __halves2bfloat162(h0, h1);
            *(__nv_bfloat162*)&g_ks[(size_t)m*768 + c] = hh;
            *(__nv_bfloat162*)&g_ks[(size_t)m*768 + 256 + c] = __halves2bfloat162(
                __float2bfloat16(v0 - bf2f(h0)), __float2bfloat16(v1 - bf2f(h1)));
            *(__nv_bfloat162*)&g_ks[(size_t)m*768 + 512 + c] = hh;
        } else {
            *(float2*)&g_v[(size_t)m*256 + n - 512] = make_float2(v0, v1);
        }
    }
};
struct EOutT {
    const float* bias;
    __device__ void st2(int m, int n, int z, float v0, float v1) const {
        *(float2*)&g_qa[(size_t)m*256 + n] = make_float2(v0 + bias[n], v1 + bias[n+1]);
    }
};
struct ESQ {
    __device__ void st2(int m, int n, int z, float v0, float v1) const {
        __nv_bfloat16 h0 = __float2bfloat16(v0), h1 = __float2bfloat16(v1);
        __nv_bfloat16 l0 = __float2bfloat16(v0 - bf2f(h0)), l1 = __float2bfloat16(v1 - bf2f(h1));
        if (n < 64) {
            *(__nv_bfloat162*)&g_uphi[(size_t)m*64 + n] = __halves2bfloat162(h0, h1);
            *(__nv_bfloat162*)&g_uplo[(size_t)m*64 + n] = __halves2bfloat162(l0, l1);
        } else {
            int nl = n - 64;
            __nv_bfloat162 hh = __halves2bfloat162(h0, h1);
            *(__nv_bfloat162*)&g_uls2[(size_t)m*192 + nl]       = hh;
            *(__nv_bfloat162*)&g_uls2[(size_t)m*192 + 64 + nl]  = __halves2bfloat162(l0, l1);
            *(__nv_bfloat162*)&g_uls2[(size_t)m*192 + 128 + nl] = hh;
        }
    }
};
struct EY2h {
    __device__ void st2(int m, int n, int z, float v0, float v1) const {
        if (n < 192) *(float2*)&g_y2[(size_t)m*192 + n] = make_float2(v0, v1);
    }
};

// ---------------- async double-buffered HMMA GEMM ----------------
template<class EF>
__global__ __launch_bounds__(256, 2) void hgemmA(const __nv_bfloat16* __restrict__ A, int lda,
                                                 const __nv_bfloat16* __restrict__ B, int ldb,
                                                 int nch, EF ef) {
    extern __shared__ __nv_bfloat16 sm[];
    const int HBUF = 4*128*24;
    int tid = threadIdx.x, lane = tid & 31, wid = tid >> 5;
    int m0 = blockIdx.y << 7, n0 = blockIdx.x << 7;
    uint32_t sbase = smem_u32(sm);
    int wm = (wid & 3) << 5, wn = (wid >> 2) << 6;
    int gid = lane >> 2, tig = lane & 3;
    float acc[2][8][4];
#pragma unroll
    for (int mf = 0; mf < 2; mf++)
#pragma unroll
        for (int nf = 0; nf < 8; nf++)
#pragma unroll
            for (int e = 0; e < 4; e++) acc[mf][nf][e] = 0.f;

    auto prefetch = [&](int ch, int buf) {
        int k0 = ch << 6;
#pragma unroll
        for (int i = 0; i < 4; i++) {
            int idx = (i << 8) + tid;
            int r = idx >> 3, c8 = idx & 7;
            uint32_t da = sbase + (uint32_t)(((buf*2*HBUF) + (((c8 >> 1)*128 + r)*24) + ((c8 & 1) << 3)) << 1);
            CP_A16(da, A + (size_t)(m0 + r)*lda + k0 + (c8 << 3));
            CP_A16(da + (HBUF << 1), B + (size_t)(n0 + r)*ldb + k0 + (c8 << 3));
        }
        CP_COMMIT();
    };
    prefetch(0, 0);
    for (int ch = 0; ch < nch; ch++) {
        if (ch + 1 < nch) prefetch(ch + 1, (ch + 1) & 1);
        else CP_COMMIT();
        CP_WAIT1();
        __syncthreads();
        const __nv_bfloat16* As = sm + (ch & 1)*2*HBUF;
        const __nv_bfloat16* Bs = As + HBUF;
#pragma unroll
        for (int g = 0; g < 4; g++) {
            uint32_t a[2][4], b[8][2];
#pragma unroll
            for (int mf = 0; mf < 2; mf++) {
                const __nv_bfloat16* base = As + (size_t)(g*128 + wm + (mf << 4) + gid)*24 + (tig << 1);
                a[mf][0] = *(const uint32_t*)base;
                a[mf][1] = *(const uint32_t*)(base + 8*24);
                a[mf][2] = *(const uint32_t*)(base + 8);
                a[mf][3] = *(const uint32_t*)(base + 8*24 + 8);
            }
#pragma unroll
            for (int nf = 0; nf < 8; nf++) {
                const __nv_bfloat16* base = Bs + (size_t)(g*128 + wn + (nf << 3) + gid)*24 + (tig << 1);
                b[nf][0] = *(const uint32_t*)base;
                b[nf][1] = *(const uint32_t*)(base + 8);
            }
#pragma unroll
            for (int mf = 0; mf < 2; mf++)
#pragma unroll
                for (int nf = 0; nf < 8; nf++)
                    mma16816(acc[mf][nf], a[mf], b[nf]);
        }
        __syncthreads();
    }
#pragma unroll
    for (int mf = 0; mf < 2; mf++) {
        int row0 = m0 + wm + (mf << 4) + gid;
#pragma unroll
        for (int nf = 0; nf < 8; nf++) {
            int col = n0 + wn + (nf << 3) + (tig << 1);
            ef.st2(row0,     col, 0, acc[mf][nf][0], acc[mf][nf][1]);
            ef.st2(row0 + 8, col, 0, acc[mf][nf][2], acc[mf][nf][3]);
        }
    }
}

// ---------------- sync gather HMMA GEMM (conv) ----------------
struct AConv2 {
    __device__ uint4 ld8(int m, int k8, int z) const {
        uint4 zr = make_uint4(0, 0, 0, 0);
        if (k8 >= 1056) return zr;
        int seg = (k8 >= 704) ? 2 : ((k8 >= 352) ? 1 : 0);
        int kk = k8 - seg*352;
        const __nv_bfloat16* src = (seg == 1) ? g_uplo : g_uphi;
        if (kk >= 288)
            return *(const uint4*)(src + (size_t)m*64 + (kk - 288));
        int tap = kk >> 5, ki = (z << 5) + (kk & 31);
        int dy = tap/3 - 1, dx = tap - (tap/3)*3 - 1;
        int b = m >> 16, pixi = m & 65535;
        int hr = (pixi >> 8) + dy, wr = (pixi & 255) + dx;
        if ((unsigned)hr > 255u || (unsigned)wr > 255u) return zr;
        return *(const uint4*)(src + (size_t)((b << 16) + (hr << 8) + wr)*64 + ki);
    }
};
__global__ __launch_bounds__(256, 2) void hgemmS(AConv2 af, const __nv_bfloat16* __restrict__ B,
                                                 const float* __restrict__ bias) {
    __shared__ __align__(16) __nv_bfloat16 As[4][128][24];
    __shared__ __align__(16) __nv_bfloat16 Bs[4][128][24];
    int tid = threadIdx.x, lane = tid & 31, wid = tid >> 5;
    int z = blockIdx.z;
    int m0 = blockIdx.y << 7;
    const __nv_bfloat16* Bz = B + (size_t)z*128*1088;
    int wm = (wid & 3) << 5, wn = (wid >> 2) << 6;
    int gid = lane >> 2, tig = lane & 3;
    float acc[2][8][4];
#pragma unroll
    for (int mf = 0; mf < 2; mf++)
#pragma unroll
        for (int nf = 0; nf < 8; nf++)
#pragma unroll
            for (int e = 0; e < 4; e++) acc[mf][nf][e] = 0.f;

    for (int ch = 0; ch < 17; ch++) {
        int k0 = ch << 6;
#pragma unroll
        for (int i = 0; i < 4; i++) {
            int idx = (i << 8) + tid;
            int r = idx >> 3, c8 = idx & 7;
            *(uint4*)&As[c8 >> 1][r][(c8 & 1) << 3] = af.ld8(m0 + r, k0 + (c8 << 3), z);
            *(uint4*)&Bs[c8 >> 1][r][(c8 & 1) << 3] = *(const uint4*)(Bz + (size_t)r*1088 + k0 + (c8 << 3));
        }
        __syncthreads();
#pragma unroll
        for (int g = 0; g < 4; g++) {
            uint32_t a[2][4], b[8][2];
#pragma unroll
            for (int mf = 0; mf < 2; mf++) {
                const __nv_bfloat16* base = &As[g][wm + (mf << 4) + gid][tig << 1];
                a[mf][0] = *(const uint32_t*)base;
                a[mf][1] = *(const uint32_t*)(base + 8*24);
                a[mf][2] = *(const uint32_t*)(base + 8);
                a[mf][3] = *(const uint32_t*)(base + 8*24 + 8);
            }
#pragma unroll
            for (int nf = 0; nf < 8; nf++) {
                const __nv_bfloat16* base = &Bs[g][wn + (nf << 3) + gid][tig << 1];
                b[nf][0] = *(const uint32_t*)base;
                b[nf][1] = *(const uint32_t*)(base + 8);
            }
#pragma unroll
            for (int mf = 0; mf < 2; mf++)
#pragma unroll
                for (int nf = 0; nf < 8; nf++)
                    mma16816(acc[mf][nf], a[mf], b[nf]);
        }
        __syncthreads();
    }
#pragma unroll
    for (int mf = 0; mf < 2; mf++) {
        int row0 = m0 + wm + (mf << 4) + gid;
#pragma unroll
        for (int nf = 0; nf < 8; nf++) {
            int col = wn + (nf << 3) + (tig << 1);
            int c = (z << 7) + col;
            *(float2*)&g_y1[(size_t)row0*256 + c] =
                make_float2(acc[mf][nf][0] + bias[c], acc[mf][nf][1] + bias[c+1]);
            *(float2*)&g_y1[(size_t)(row0 + 8)*256 + c] =
                make_float2(acc[mf][nf][2] + bias[c], acc[mf][nf][3] + bias[c+1]);
        }
    }
}

// ---------------- GN stats / SRU / CRU glue ----------------
__global__ void gn_stats() {
    int t0 = blockIdx.x * 512;
    int c = threadIdx.x;
    const float* p = g_q + (size_t)t0*256 + c;
    float s = 0.f, s2 = 0.f;
#pragma unroll 4
    for (int i = 0; i < 512; i++) { float v = p[(size_t)i*256]; s += v; s2 += v*v; }
#pragma unroll
    for (int off = 8; off > 0; off >>= 1) {
        s  += __shfl_down_sync(0xffffffff, s,  off, 16);
        s2 += __shfl_down_sync(0xffffffff, s2, off, 16);
    }
    if ((c & 15) == 0) {
        int b = t0 >> 16, g = c >> 4;
        atomicAdd(&g_gnstats[((b << 4) + g)*2],     s);
        atomicAdd(&g_gnstats[((b << 4) + g)*2 + 1], s2);
    }
}
__global__ void sru_elem(const float* __restrict__ gn_w, const float* __restrict__ gn_b) {
    int i = blockIdx.x*256 + threadIdx.x;
    int t = i >> 7, cp = i & 127;
    int b = t >> 16;
    int c1 = cp, c2 = cp + 128;
    float wsum = g_misc[0];
    int g1 = c1 >> 4, g2 = c2 >> 4;
    float m1 = g_gnstats[((b<<4)+g1)*2] / GN_N;
    float v1 = g_gnstats[((b<<4)+g1)*2+1] / GN_N - m1*m1;
    float m2 = g_gnstats[((b<<4)+g2)*2] / GN_N;
    float v2 = g_gnstats[((b<<4)+g2)*2+1] / GN_N - m2*m2;
    float w1c = gn_w[c1], w2c = gn_w[c2];
    float A1 = rsqrtf(v1 + 1e-5f)*w1c, B1 = gn_b[c1] - m1*rsqrtf(v1 + 1e-5f)*w1c;
    float A2 = rsqrtf(v2 + 1e-5f)*w2c, B2 = gn_b[c2] - m2*rsqrtf(v2 + 1e-5f)*w2c;
    float x1 = g_q[(size_t)t*256 + c1], x2 = g_q[(size_t)t*256 + c2];
    float rw1 = 1.0f/(1.0f + expf(-(x1*A1 + B1)*(w1c/wsum)));
    float rw2 = 1.0f/(1.0f + expf(-(x2*A2 + B2)*(w2c/wsum)));
    float w11 = rw1 > 0.5f ? 1.0f : rw1, w21 = rw1 > 0.5f ? 0.0f : rw1;
    float w12 = rw2 > 0.5f ? 1.0f : rw2, w22 = rw2 > 0.5f ? 0.0f : rw2;
    g_qa[(size_t)t*256 + c1] = w11*x1 + w22*x2;
    g_qa[(size_t)t*256 + c2] = w12*x2 + w21*x1;
}
__global__ void pool_kernel() {
    int t0 = blockIdx.x * 256;
    int b = t0 >> 16;
    int tid = threadIdx.x;
    float a1 = 0.f, a2 = 0.f, a3 = 0.f;
    for (int t = t0; t < t0 + 256; t++) {
        a1 += g_y1[(size_t)t*256 + tid];
        if (tid < 192) a2 += g_y2[(size_t)t*192 + tid];
        if (tid < 64)  a3 += bf2f(g_uls2[(size_t)t*192 + tid]) + bf2f(g_uls2[(size_t)t*192 + 64 + tid]);
    }
    atomicAdd(&g_pool[(b << 9) + tid], a1);
    if (tid < 192) atomicAdd(&g_pool[(b << 9) + 256 + tid], a2);
    if (tid < 64)  atomicAdd(&g_pool[(b << 9) + 448 + tid], a3);
}
__global__ void softmax512() {
    int b = blockIdx.x, t = threadIdx.x;
    __shared__ float sh[512];
    float v = g_pool[(b << 9) + t] * (1.0f/65536.0f);
    sh[t] = v;
    __syncthreads();
    for (int st = 256; st > 0; st >>= 1) { if (t < st) sh[t] = fmaxf(sh[t], sh[t + st]); __syncthreads(); }
    float mx = sh[0];
    __syncthreads();
    float e = expf(v - mx);
    sh[t] = e;
    __syncthreads();
    for (int st = 256; st > 0; st >>= 1) { if (t < st) sh[t] += sh[t + st]; __syncthreads(); }
    float sum = sh[0];
    __syncthreads();
    g_pool[(b << 9) + t] = e / sum;
}
__global__ void cru_combine() {
    int i = blockIdx.x*256 + threadIdx.x;
    int t = i >> 8, c = i & 255;
    int b = t >> 16;
    float y1 = g_y1[i];
    float y2v;
    if (c < 192) y2v = g_y2[(size_t)t*192 + c];
    else {
        int nl = c - 192;
        y2v = bf2f(g_uls2[(size_t)t*192 + nl]) + bf2f(g_uls2[(size_t)t*192 + 64 + nl]);
    }
    g_ka[(size_t)t*256 + c] = g_pool[(b << 9) + c]*y1 + g_pool[(b << 9) + 256 + c]*y2v;
}

// ---------------- windowed attention ----------------
__global__ __launch_bounds__(64) void attn(const float* __restrict__ rel_pos) {
    int win = blockIdx.x, h = blockIdx.y, b = blockIdx.z;
    __shared__ __align__(16) float ksh[2048];
    __shared__ __align__(16) float vsh[2048];
    __shared__ float rp[225];
    int wy = win >> 5, wx = win & 31;
    int t0 = (b << 16) + (wy << 11) + (wx << 3);
    int tid = threadIdx.x;
    int hb = h << 5;
    for (int i = tid; i < 2048; i += 64) {
        int p = i >> 5, d = i & 31;
        int t = t0 + ((p >> 3) << 8) + (p & 7);
        ksh[i] = g_ka[(size_t)t*256 + hb + d];
        vsh[i] = g_v [(size_t)t*256 + hb + d];
    }
    for (int i = tid; i < 225; i += 64) rp[i] = rel_pos[h*225 + i];
    __syncthreads();
    int myt = t0 + ((tid >> 3) << 8) + (tid & 7);
    ull qp[16];
#pragma unroll
    for (int d = 0; d < 16; d++) {
        float2 qv = *(const float2*)&g_qa[(size_t)myt*256 + hb + 2*d];
        qp[d] = pack2(qv.x, qv.y);
    }
    int ph = tid >> 3, pw = tid & 7;
    bool lr = wy == 31, lc = wx == 31;
    ull zz = pack2(0.f, 0.f);
    float s[64];
#pragma unroll
    for (int qi = 0; qi < 64; qi++) {
        const ull* kp = (const ull*)&ksh[qi*32];
        ull dp = zz;
#pragma unroll
        for (int d = 0; d < 16; d++) ffma2(dp, qp[d], kp[d]);
        float dl, dh;
        unpack2(dp, dl, dh);
        int qh = qi >> 3, qw = qi & 7;
        float val = (dl + dh)*SCALE + rp[(ph - qh + 7)*15 + (pw - qw + 7)];
        if ((lr && ((ph < 4) != (qh < 4))) || (lc && ((pw < 4) != (qw < 4)))) val = -1e30f;
        s[qi] = val;
    }
    float mx = -1e30f;
#pragma unroll
    for (int qi = 0; qi < 64; qi++) mx = fmaxf(mx, s[qi]);
    float sum = 0.f;
#pragma unroll
    for (int qi = 0; qi < 64; qi++) { s[qi] = expf(s[qi] - mx); sum += s[qi]; }
    float inv = 1.0f / sum;
    ull accp[16];
#pragma unroll
    for (int d = 0; d < 16; d++) accp[d] = zz;
#pragma unroll
    for (int qi = 0; qi < 64; qi++) {
        ull wd = pack2(s[qi]*inv, s[qi]*inv);
        const ull* vp = (const ull*)&vsh[qi*32];
#pragma unroll
        for (int d = 0; d < 16; d++) ffma2(accp[d], wd, vp[d]);
    }
    float af[32];
#pragma unroll
    for (int d = 0; d < 16; d++) unpack2(accp[d], af[2*d], af[2*d+1]);
    __nv_bfloat16* dst = &g_atts[(size_t)myt*768];
#pragma unroll
    for (int d0 = 0; d0 < 32; d0 += 8) {
        __nv_bfloat16 hv[8], lv[8];
#pragma unroll
        for (int e = 0; e < 8; e++) {
            hv[e] = __float2bfloat16(af[d0 + e]);
            lv[e] = __float2bfloat16(af[d0 + e] - bf2f(hv[e]));
        }
        *(uint4*)&dst[hb + d0]       = *(uint4*)hv;
        *(uint4*)&dst[256 + hb + d0] = *(uint4*)lv;
        *(uint4*)&dst[512 + hb + d0] = *(uint4*)hv;
    }
}

// ---------------- final un-roll scatter to NCHW ----------------
__global__ __launch_bounds__(256) void unscatter(float* __restrict__ out) {
    __shared__ float s2[32][261];
    int bid = blockIdx.x;
    int b = bid >> 11, rem = bid & 2047;
    int hr = rem >> 3, w0 = (rem & 7) << 5;
    int tid = threadIdx.x;
    size_t tbase = (size_t)(b << 16) + (hr << 8) + w0;
    for (int i = 0; i < 8; i++) {
        int idx = (i << 8) + tid;
        int tw = idx >> 6, c4 = idx & 63;
        float4 v = *(const float4*)&g_qa[(tbase + tw)*256 + (c4 << 2)];
        s2[tw][(c4 << 2)]     = v.x;
        s2[tw][(c4 << 2) + 1] = v.y;
        s2[tw][(c4 << 2) + 2] = v.z;
        s2[tw][(c4 << 2) + 3] = v.w;
    }
    __syncthreads();
    int hs = ((hr + 4) & 255) << 8;
    for (int i = 0; i < 32; i++) {
        int idx = (i << 8) + tid;
        int c = idx >> 5, wp = idx & 31;
        out[(size_t)((b << 8) + c)*65536 + hs + ((w0 + wp + 4) & 255)] = s2[wp][c];
    }
}

// ---------------- launch ----------------
extern "C" void kernel_launch(void* const* d_in, const int* in_sizes, int n_in,
                              void* d_out, int out_size) {
    const float* x      = (const float*)d_in[0];
    const float* w_qkv  = (const float*)d_in[1];
    const float* b_qkv  = (const float*)d_in[2];
    const float* rel_pos= (const float*)d_in[3];
    const float* gn_w   = (const float*)d_in[4];
    const float* gn_b   = (const float*)d_in[5];
    const float* sq1    = (const float*)d_in[6];
    const float* sq2    = (const float*)d_in[7];
    const float* gwc    = (const float*)d_in[8];
    const float* gwc_b  = (const float*)d_in[9];
    const float* pwc1   = (const float*)d_in[10];
    const float* pwc2   = (const float*)d_in[11];
    const float* w_out  = (const float*)d_in[12];
    const float* b_out  = (const float*)d_in[13];
    float* out = (float*)d_out;

    __nv_bfloat16 *p_bq, *p_bout, *p_bsq, *p_bconv2, *p_bpwc2n, *p_xs, *p_ks, *p_atts, *p_uls2;
    cudaGetSymbolAddress((void**)&p_bq,     g_bq);
    cudaGetSymbolAddress((void**)&p_bout,   g_bout);
    cudaGetSymbolAddress((void**)&p_bsq,    g_bsq);
    cudaGetSymbolAddress((void**)&p_bconv2, g_bconv2);
    cudaGetSymbolAddress((void**)&p_bpwc2n, g_bpwc2n);
    cudaGetSymbolAddress((void**)&p_xs,     g_xs);
    cudaGetSymbolAddress((void**)&p_ks,     g_ks);
    cudaGetSymbolAddress((void**)&p_atts,   g_atts);
    cudaGetSymbolAddress((void**)&p_uls2,   g_uls2);

    const int DSM = 98304;  // 2 buffers x (A+B) x 4x128x24 bf16
    cudaFuncSetAttribute(hgemmA<EQKVt>, cudaFuncAttributeMaxDynamicSharedMemorySize, DSM);
    cudaFuncSetAttribute(hgemmA<EOutT>, cudaFuncAttributeMaxDynamicSharedMemorySize, DSM);
    cudaFuncSetAttribute(hgemmA<ESQ>,   cudaFuncAttributeMaxDynamicSharedMemorySize, DSM);
    cudaFuncSetAttribute(hgemmA<EY2h>,  cudaFuncAttributeMaxDynamicSharedMemorySize, DSM);

    zero_small<<<4, 256>>>();                                          // 0
    prep_bw<<<(768*768 + 255)/256, 256>>>(w_qkv, p_bq, 768);           // 1
    xsplit<<<4096, 256>>>(x);                                          // 2
    hgemmA<EQKVt><<<dim3(6, 1024), 256, DSM>>>(p_xs, 768, p_bq, 768, 12, EQKVt{b_qkv});  // 3 (profiled)

    gn_stats<<<256, 256>>>();
    sum_gnw<<<1, 256>>>(gn_w);
    sru_elem<<<65536, 256>>>(gn_w, gn_b);

    prep_bsq<<<(128*768 + 255)/256, 256>>>(sq1, sq2);
    hgemmA<ESQ><<<dim3(1, 1024), 256, DSM>>>(p_ks, 768, p_bsq, 768, 12, ESQ{});
    prep_bconv2<<<(2*128*1088 + 255)/256, 256>>>(gwc, pwc1);
    hgemmS<<<dim3(1, 1024, 2), 256>>>(AConv2{}, p_bconv2, gwc_b);
    prep_bpwc2n<<<(256*192 + 255)/256, 256>>>(pwc2);
    hgemmA<EY2h><<<dim3(2, 1024), 256, DSM>>>(p_uls2, 192, p_bpwc2n, 192, 3, EY2h{});

    pool_kernel<<<512, 256>>>();
    softmax512<<<2, 512>>>();
    cru_combine<<<131072, 256>>>();

    attn<<<dim3(1024, 8, 2), 64>>>(rel_pos);
    prep_bw<<<(256*768 + 255)/256, 256>>>(w_out, p_bout, 256);
    hgemmA<EOutT><<<dim3(2, 1024), 256, DSM>>>(p_atts, 768, p_bout, 768, 12, EOutT{b_out});
    unscatter<<<4096, 256>>>(out);
}

// round 8
// speedup vs baseline: 1.5939x; 1.0285x over previous
#include <cuda_runtime.h>
#include <cuda_bf16.h>
#include <math.h>
#include <cstdint>

#define TTOT 131072
#define SCALE 0.17677669529663687f
#define GN_N 1048576.0f

typedef unsigned long long ull;

__device__ __forceinline__ ull pack2(float a, float b) {
    ull r; asm("mov.b64 %0, {%1, %2};" : "=l"(r) : "f"(a), "f"(b)); return r;
}
__device__ __forceinline__ void unpack2(ull p, float& a, float& b) {
    asm("mov.b64 {%0, %1}, %2;" : "=f"(a), "=f"(b) : "l"(p));
}
__device__ __forceinline__ void ffma2(ull& d, ull a, ull b) {
    asm("fma.rn.f32x2 %0, %1, %2, %0;" : "+l"(d) : "l"(a), "l"(b));
}
__device__ __forceinline__ void mma16816(float* d, const uint32_t* a, const uint32_t* b) {
    asm volatile("mma.sync.aligned.m16n8k16.row.col.f32.bf16.bf16.f32 "
        "{%0,%1,%2,%3}, {%4,%5,%6,%7}, {%8,%9}, {%0,%1,%2,%3};"
        : "+f"(d[0]), "+f"(d[1]), "+f"(d[2]), "+f"(d[3])
        : "r"(a[0]), "r"(a[1]), "r"(a[2]), "r"(a[3]), "r"(b[0]), "r"(b[1]));
}
__device__ __forceinline__ void ldsm4(uint32_t& r0, uint32_t& r1, uint32_t& r2, uint32_t& r3,
                                      uint32_t addr) {
    asm volatile("ldmatrix.sync.aligned.m8n8.x4.shared.b16 {%0,%1,%2,%3}, [%4];"
                 : "=r"(r0), "=r"(r1), "=r"(r2), "=r"(r3) : "r"(addr));
}
__device__ __forceinline__ uint32_t smem_u32(const void* p) {
    uint32_t a;
    asm("{ .reg .u64 t; cvta.to.shared.u64 t, %1; cvt.u32.u64 %0, t; }" : "=r"(a) : "l"(p));
    return a;
}
__device__ __forceinline__ float bf2f(__nv_bfloat16 h) { return __bfloat162float(h); }

#define CP_A16(d, s) asm volatile("cp.async.cg.shared.global [%0], [%1], 16;" :: "r"(d), "l"(s) : "memory")
#define CP_COMMIT()  asm volatile("cp.async.commit_group;" ::: "memory")
#define CP_WAIT1()   asm volatile("cp.async.wait_group 1;" ::: "memory")

// ---------------- scratch ----------------
__device__ __nv_bfloat16 g_xs  [(size_t)TTOT*768];
__device__ __nv_bfloat16 g_ks  [(size_t)TTOT*768];
__device__ __nv_bfloat16 g_atts[(size_t)TTOT*768];
__device__ __nv_bfloat16 g_uphi[(size_t)TTOT*64];
__device__ __nv_bfloat16 g_uplo[(size_t)TTOT*64];
__device__ __nv_bfloat16 g_uls2[(size_t)TTOT*192];
__device__ float g_q  [(size_t)TTOT*256];
__device__ float g_v  [(size_t)TTOT*256];
__device__ float g_qa [(size_t)TTOT*256];
__device__ float g_ka [(size_t)TTOT*256];
__device__ float g_y1 [(size_t)TTOT*256];
__device__ float g_y2 [(size_t)TTOT*192];
__device__ __nv_bfloat16 g_bq    [768*768];
__device__ __nv_bfloat16 g_bout  [256*768];
__device__ __nv_bfloat16 g_bsq   [128*768];
__device__ __nv_bfloat16 g_bconv2[2*128*1088];
__device__ __nv_bfloat16 g_bpwc2n[256*192];
__device__ float g_gnstats[2*16*2];
__device__ float g_pool[2*512];
__device__ float g_misc[4];

// ---------------- small utilities ----------------
__global__ void zero_small() {
    int i = blockIdx.x*256 + threadIdx.x;
    if (i < 1024) g_pool[i] = 0.f;
    if (i < 64)   g_gnstats[i] = 0.f;
}
__global__ void sum_gnw(const float* __restrict__ gn_w) {
    __shared__ float sh[256];
    sh[threadIdx.x] = gn_w[threadIdx.x];
    __syncthreads();
    for (int st = 128; st > 0; st >>= 1) {
        if (threadIdx.x < st) sh[threadIdx.x] += sh[threadIdx.x + st];
        __syncthreads();
    }
    if (threadIdx.x == 0) g_misc[0] = sh[0];
}
__global__ void prep_bw(const float* __restrict__ w, __nv_bfloat16* __restrict__ dst, int N) {
    int i = blockIdx.x*256 + threadIdx.x;
    if (i >= N*768) return;
    int n = i / 768, kp = i % 768;
    int seg = kp >> 8, kk = kp & 255;
    float v = w[n*256 + kk];
    __nv_bfloat16 h = __float2bfloat16(v);
    dst[i] = (seg == 2) ? __float2bfloat16(v - bf2f(h)) : h;
}
__global__ void prep_bsq(const float* __restrict__ sq1, const float* __restrict__ sq2) {
    int i = blockIdx.x*256 + threadIdx.x;
    if (i >= 128*768) return;
    int n = i / 768, kp = i % 768;
    int seg = kp >> 8, kk = kp & 255;
    float w = 0.f;
    if (n < 64)  { if (kk < 128)  w = sq1[n*128 + kk]; }
    else         { if (kk >= 128) w = sq2[(n-64)*128 + (kk-128)]; }
    __nv_bfloat16 h = __float2bfloat16(w);
    g_bsq[i] = (seg == 2) ? __float2bfloat16(w - bf2f(h)) : h;
}
__global__ void prep_bconv2(const float* __restrict__ gwc, const float* __restrict__ pwc1) {
    int i = blockIdx.x*256 + threadIdx.x;
    if (i >= 2*128*1088) return;
    int z = i / (128*1088), r = i % (128*1088);
    int n = r / 1088, kp = r % 1088;
    float w = 0.f; int seg = 0;
    if (kp < 1056) {
        seg = kp / 352;
        int kk = kp - seg*352;
        int c = z*128 + n;
        if (kk < 288) { int tap = kk >> 5, kl = kk & 31; w = gwc[c*288 + kl*9 + tap]; }
        else          w = pwc1[c*64 + kk - 288];
    }
    __nv_bfloat16 h = __float2bfloat16(w);
    g_bconv2[i] = (seg == 2) ? __float2bfloat16(w - bf2f(h)) : h;
}
__global__ void prep_bpwc2n(const float* __restrict__ pwc2) {
    int i = blockIdx.x*256 + threadIdx.x;
    if (i >= 256*192) return;
    int n = i / 192, kp = i % 192;
    int seg = kp >> 6, kk = kp & 63;
    float w = (n < 192) ? pwc2[n*64 + kk] : 0.f;
    __nv_bfloat16 h = __float2bfloat16(w);
    g_bpwc2n[i] = (seg == 2) ? __float2bfloat16(w - bf2f(h)) : h;
}

// ---------------- roll + split x ----------------
__global__ __launch_bounds__(256) void xsplit(const float* __restrict__ x) {
    __shared__ float s[256][33];
    int bid = blockIdx.x;
    int b = bid >> 11, rem = bid & 2047;
    int hr = rem >> 3, w0 = (rem & 7) << 5;
    int tid = threadIdx.x, wid = tid >> 5, lane = tid & 31;
    int hs = ((hr + 4) & 255) << 8;
    for (int i = 0; i < 32; i++) {
        int idx = (i << 8) + tid;
        int c = idx >> 5, wp = idx & 31;
        s[c][wp] = x[(size_t)((b << 8) + c)*65536 + hs + ((w0 + wp + 4) & 255)];
    }
    __syncthreads();
    size_t t = (size_t)(b << 16) + (hr << 8) + w0 + lane;
    int c0 = wid << 5;
    __nv_bfloat16* dst = &g_xs[t*768];
    for (int j = 0; j < 32; j += 8) {
        __nv_bfloat16 hv[8], lv[8];
#pragma unroll
        for (int e = 0; e < 8; e++) {
            float a = s[c0 + j + e][lane];
            hv[e] = __float2bfloat16(a);
            lv[e] = __float2bfloat16(a - bf2f(hv[e]));
        }
        *(uint4*)&dst[c0 + j]       = *(uint4*)hv;
        *(uint4*)&dst[256 + c0 + j] = *(uint4*)lv;
        *(uint4*)&dst[512 + c0 + j] = *(uint4*)hv;
    }
}

// ---------------- epilogues ----------------
struct EQKVt {
    const float* bias;
    __device__ void st2(int m, int n, int z, float v0, float v1) const {
        v0 += bias[n]; v1 += bias[n+1];
        if (n < 256) {
            *(float2*)&g_q[(size_t)m*256 + n] = make_float2(v0, v1);
        } else if (n < 512) {
            int c = n - 256;
            __nv_bfloat16 h0 = __float2bfloat16(v0), h1 = __float2bfloat16(v1);
            __nv_bfloat162 hh = __halves2bfloat162(h0, h1);
            *(__nv_bfloat162*)&g_ks[(size_t)m*768 + c] = hh;
            *(__nv_bfloat162*)&g_ks[(size_t)m*768 + 256 + c] = __halves2bfloat162(
                __float2bfloat16(v0 - bf2f(h0)), __float2bfloat16(v1 - bf2f(h1)));
            *(__nv_bfloat162*)&g_ks[(size_t)m*768 + 512 + c] = hh;
        } else {
            *(float2*)&g_v[(size_t)m*256 + n - 512] = make_float2(v0, v1);
        }
    }
};
struct EOutT {
    const float* bias;
    __device__ void st2(int m, int n, int z, float v0, float v1) const {
        *(float2*)&g_qa[(size_t)m*256 + n] = make_float2(v0 + bias[n], v1 + bias[n+1]);
    }
};
struct ESQ {
    __device__ void st2(int m, int n, int z, float v0, float v1) const {
        __nv_bfloat16 h0 = __float2bfloat16(v0), h1 = __float2bfloat16(v1);
        __nv_bfloat16 l0 = __float2bfloat16(v0 - bf2f(h0)), l1 = __float2bfloat16(v1 - bf2f(h1));
        if (n < 64) {
            *(__nv_bfloat162*)&g_uphi[(size_t)m*64 + n] = __halves2bfloat162(h0, h1);
            *(__nv_bfloat162*)&g_uplo[(size_t)m*64 + n] = __halves2bfloat162(l0, l1);
        } else {
            int nl = n - 64;
            __nv_bfloat162 hh = __halves2bfloat162(h0, h1);
            *(__nv_bfloat162*)&g_uls2[(size_t)m*192 + nl]       = hh;
            *(__nv_bfloat162*)&g_uls2[(size_t)m*192 + 64 + nl]  = __halves2bfloat162(l0, l1);
            *(__nv_bfloat162*)&g_uls2[(size_t)m*192 + 128 + nl] = hh;
        }
    }
};
struct EY2h {
    __device__ void st2(int m, int n, int z, float v0, float v1) const {
        if (n < 192) *(float2*)&g_y2[(size_t)m*192 + n] = make_float2(v0, v1);
    }
};

// ---------------- async double-buffered HMMA GEMM (ldmatrix frags) ----------------
template<class EF>
__global__ __launch_bounds__(256, 2) void hgemmA(const __nv_bfloat16* __restrict__ A, int lda,
                                                 const __nv_bfloat16* __restrict__ B, int ldb,
                                                 int nch, EF ef) {
    extern __shared__ __nv_bfloat16 sm[];
    const int HBUF = 4*128*24;           // elements per (A or B) buffer
    int tid = threadIdx.x, lane = tid & 31, wid = tid >> 5;
    int m0 = blockIdx.y << 7, n0 = blockIdx.x << 7;
    uint32_t sbase = smem_u32(sm);
    int wm = (wid & 3) << 5, wn = (wid >> 2) << 6;
    int gid = lane >> 2, tig = lane & 3;
    // ldmatrix lane-address offsets (bytes, relative to group base)
    int lr = lane & 7, lh = (lane >> 3) & 1, lk = lane >> 4;   // A: row-half, k-half
    uint32_t offA[2];
#pragma unroll
    for (int mf = 0; mf < 2; mf++)
        offA[mf] = (uint32_t)(((wm + (mf << 4) + lr + lh*8)*24 + lk*8) << 1);
    int lq = lane >> 3;                                        // B quadrant
    uint32_t offB[4];
#pragma unroll
    for (int p = 0; p < 4; p++)
        offB[p] = (uint32_t)(((wn + (p << 4) + lr + (lq >> 1)*8)*24 + (lq & 1)*8) << 1);

    float acc[2][8][4];
#pragma unroll
    for (int mf = 0; mf < 2; mf++)
#pragma unroll
        for (int nf = 0; nf < 8; nf++)
#pragma unroll
            for (int e = 0; e < 4; e++) acc[mf][nf][e] = 0.f;

    auto prefetch = [&](int ch, int buf) {
        int k0 = ch << 6;
#pragma unroll
        for (int i = 0; i < 4; i++) {
            int idx = (i << 8) + tid;
            int r = idx >> 3, c8 = idx & 7;
            uint32_t da = sbase + (uint32_t)(((buf*2*HBUF) + (((c8 >> 1)*128 + r)*24) + ((c8 & 1) << 3)) << 1);
            CP_A16(da, A + (size_t)(m0 + r)*lda + k0 + (c8 << 3));
            CP_A16(da + (HBUF << 1), B + (size_t)(n0 + r)*ldb + k0 + (c8 << 3));
        }
        CP_COMMIT();
    };
    prefetch(0, 0);
    for (int ch = 0; ch < nch; ch++) {
        if (ch + 1 < nch) prefetch(ch + 1, (ch + 1) & 1);
        else CP_COMMIT();
        CP_WAIT1();
        __syncthreads();
        uint32_t bufb = sbase + (uint32_t)((ch & 1)*2*HBUF << 1);
#pragma unroll
        for (int g = 0; g < 4; g++) {
            uint32_t abase = bufb + (uint32_t)(g*6144);
            uint32_t bbase = abase + (uint32_t)(HBUF << 1);
            uint32_t a[2][4], b[8][2];
            ldsm4(a[0][0], a[0][1], a[0][2], a[0][3], abase + offA[0]);
            ldsm4(a[1][0], a[1][1], a[1][2], a[1][3], abase + offA[1]);
            ldsm4(b[0][0], b[0][1], b[1][0], b[1][1], bbase + offB[0]);
            ldsm4(b[2][0], b[2][1], b[3][0], b[3][1], bbase + offB[1]);
            ldsm4(b[4][0], b[4][1], b[5][0], b[5][1], bbase + offB[2]);
            ldsm4(b[6][0], b[6][1], b[7][0], b[7][1], bbase + offB[3]);
#pragma unroll
            for (int mf = 0; mf < 2; mf++)
#pragma unroll
                for (int nf = 0; nf < 8; nf++)
                    mma16816(acc[mf][nf], a[mf], b[nf]);
        }
        __syncthreads();
    }
#pragma unroll
    for (int mf = 0; mf < 2; mf++) {
        int row0 = m0 + wm + (mf << 4) + gid;
#pragma unroll
        for (int nf = 0; nf < 8; nf++) {
            int col = n0 + wn + (nf << 3) + (tig << 1);
            ef.st2(row0,     col, 0, acc[mf][nf][0], acc[mf][nf][1]);
            ef.st2(row0 + 8, col, 0, acc[mf][nf][2], acc[mf][nf][3]);
        }
    }
}

// ---------------- sync gather HMMA GEMM (conv, ldmatrix frags) ----------------
struct AConv2 {
    __device__ uint4 ld8(int m, int k8, int z) const {
        uint4 zr = make_uint4(0, 0, 0, 0);
        if (k8 >= 1056) return zr;
        int seg = (k8 >= 704) ? 2 : ((k8 >= 352) ? 1 : 0);
        int kk = k8 - seg*352;
        const __nv_bfloat16* src = (seg == 1) ? g_uplo : g_uphi;
        if (kk >= 288)
            return *(const uint4*)(src + (size_t)m*64 + (kk - 288));
        int tap = kk >> 5, ki = (z << 5) + (kk & 31);
        int dy = tap/3 - 1, dx = tap - (tap/3)*3 - 1;
        int b = m >> 16, pixi = m & 65535;
        int hr = (pixi >> 8) + dy, wr = (pixi & 255) + dx;
        if ((unsigned)hr > 255u || (unsigned)wr > 255u) return zr;
        return *(const uint4*)(src + (size_t)((b << 16) + (hr << 8) + wr)*64 + ki);
    }
};
__global__ __launch_bounds__(256, 2) void hgemmS(AConv2 af, const __nv_bfloat16* __restrict__ B,
                                                 const float* __restrict__ bias) {
    __shared__ __align__(16) __nv_bfloat16 As[4][128][24];
    __shared__ __align__(16) __nv_bfloat16 Bs[4][128][24];
    int tid = threadIdx.x, lane = tid & 31, wid = tid >> 5;
    int z = blockIdx.z;
    int m0 = blockIdx.y << 7;
    const __nv_bfloat16* Bz = B + (size_t)z*128*1088;
    int wm = (wid & 3) << 5, wn = (wid >> 2) << 6;
    int gid = lane >> 2, tig = lane & 3;
    uint32_t sA = smem_u32(&As[0][0][0]), sB = smem_u32(&Bs[0][0][0]);
    int lr = lane & 7, lh = (lane >> 3) & 1, lk = lane >> 4;
    uint32_t offA[2];
#pragma unroll
    for (int mf = 0; mf < 2; mf++)
        offA[mf] = (uint32_t)(((wm + (mf << 4) + lr + lh*8)*24 + lk*8) << 1);
    int lq = lane >> 3;
    uint32_t offB[4];
#pragma unroll
    for (int p = 0; p < 4; p++)
        offB[p] = (uint32_t)(((wn + (p << 4) + lr + (lq >> 1)*8)*24 + (lq & 1)*8) << 1);

    float acc[2][8][4];
#pragma unroll
    for (int mf = 0; mf < 2; mf++)
#pragma unroll
        for (int nf = 0; nf < 8; nf++)
#pragma unroll
            for (int e = 0; e < 4; e++) acc[mf][nf][e] = 0.f;

    for (int ch = 0; ch < 17; ch++) {
        int k0 = ch << 6;
#pragma unroll
        for (int i = 0; i < 4; i++) {
            int idx = (i << 8) + tid;
            int r = idx >> 3, c8 = idx & 7;
            *(uint4*)&As[c8 >> 1][r][(c8 & 1) << 3] = af.ld8(m0 + r, k0 + (c8 << 3), z);
            *(uint4*)&Bs[c8 >> 1][r][(c8 & 1) << 3] = *(const uint4*)(Bz + (size_t)r*1088 + k0 + (c8 << 3));
        }
        __syncthreads();
#pragma unroll
        for (int g = 0; g < 4; g++) {
            uint32_t abase = sA + (uint32_t)(g*6144);
            uint32_t bbase = sB + (uint32_t)(g*6144);
            uint32_t a[2][4], b[8][2];
            ldsm4(a[0][0], a[0][1], a[0][2], a[0][3], abase + offA[0]);
            ldsm4(a[1][0], a[1][1], a[1][2], a[1][3], abase + offA[1]);
            ldsm4(b[0][0], b[0][1], b[1][0], b[1][1], bbase + offB[0]);
            ldsm4(b[2][0], b[2][1], b[3][0], b[3][1], bbase + offB[1]);
            ldsm4(b[4][0], b[4][1], b[5][0], b[5][1], bbase + offB[2]);
            ldsm4(b[6][0], b[6][1], b[7][0], b[7][1], bbase + offB[3]);
#pragma unroll
            for (int mf = 0; mf < 2; mf++)
#pragma unroll
                for (int nf = 0; nf < 8; nf++)
                    mma16816(acc[mf][nf], a[mf], b[nf]);
        }
        __syncthreads();
    }
#pragma unroll
    for (int mf = 0; mf < 2; mf++) {
        int row0 = m0 + wm + (mf << 4) + gid;
#pragma unroll
        for (int nf = 0; nf < 8; nf++) {
            int col = wn + (nf << 3) + (tig << 1);
            int c = (z << 7) + col;
            *(float2*)&g_y1[(size_t)row0*256 + c] =
                make_float2(acc[mf][nf][0] + bias[c], acc[mf][nf][1] + bias[c+1]);
            *(float2*)&g_y1[(size_t)(row0 + 8)*256 + c] =
                make_float2(acc[mf][nf][2] + bias[c], acc[mf][nf][3] + bias[c+1]);
        }
    }
}

// ---------------- GN stats / SRU / CRU glue ----------------
__global__ void gn_stats() {
    int t0 = blockIdx.x * 512;
    int c = threadIdx.x;
    const float* p = g_q + (size_t)t0*256 + c;
    float s = 0.f, s2 = 0.f;
#pragma unroll 4
    for (int i = 0; i < 512; i++) { float v = p[(size_t)i*256]; s += v; s2 += v*v; }
#pragma unroll
    for (int off = 8; off > 0; off >>= 1) {
        s  += __shfl_down_sync(0xffffffff, s,  off, 16);
        s2 += __shfl_down_sync(0xffffffff, s2, off, 16);
    }
    if ((c & 15) == 0) {
        int b = t0 >> 16, g = c >> 4;
        atomicAdd(&g_gnstats[((b << 4) + g)*2],     s);
        atomicAdd(&g_gnstats[((b << 4) + g)*2 + 1], s2);
    }
}
__global__ void sru_elem(const float* __restrict__ gn_w, const float* __restrict__ gn_b) {
    int i = blockIdx.x*256 + threadIdx.x;
    int t = i >> 7, cp = i & 127;
    int b = t >> 16;
    int c1 = cp, c2 = cp + 128;
    float wsum = g_misc[0];
    int g1 = c1 >> 4, g2 = c2 >> 4;
    float m1 = g_gnstats[((b<<4)+g1)*2] / GN_N;
    float v1 = g_gnstats[((b<<4)+g1)*2+1] / GN_N - m1*m1;
    float m2 = g_gnstats[((b<<4)+g2)*2] / GN_N;
    float v2 = g_gnstats[((b<<4)+g2)*2+1] / GN_N - m2*m2;
    float w1c = gn_w[c1], w2c = gn_w[c2];
    float A1 = rsqrtf(v1 + 1e-5f)*w1c, B1 = gn_b[c1] - m1*rsqrtf(v1 + 1e-5f)*w1c;
    float A2 = rsqrtf(v2 + 1e-5f)*w2c, B2 = gn_b[c2] - m2*rsqrtf(v2 + 1e-5f)*w2c;
    float x1 = g_q[(size_t)t*256 + c1], x2 = g_q[(size_t)t*256 + c2];
    float rw1 = 1.0f/(1.0f + expf(-(x1*A1 + B1)*(w1c/wsum)));
    float rw2 = 1.0f/(1.0f + expf(-(x2*A2 + B2)*(w2c/wsum)));
    float w11 = rw1 > 0.5f ? 1.0f : rw1, w21 = rw1 > 0.5f ? 0.0f : rw1;
    float w12 = rw2 > 0.5f ? 1.0f : rw2, w22 = rw2 > 0.5f ? 0.0f : rw2;
    g_qa[(size_t)t*256 + c1] = w11*x1 + w22*x2;
    g_qa[(size_t)t*256 + c2] = w12*x2 + w21*x1;
}
__global__ void pool_kernel() {
    int t0 = blockIdx.x * 256;
    int b = t0 >> 16;
    int tid = threadIdx.x;
    float a1 = 0.f, a2 = 0.f, a3 = 0.f;
    for (int t = t0; t < t0 + 256; t++) {
        a1 += g_y1[(size_t)t*256 + tid];
        if (tid < 192) a2 += g_y2[(size_t)t*192 + tid];
        if (tid < 64)  a3 += bf2f(g_uls2[(size_t)t*192 + tid]) + bf2f(g_uls2[(size_t)t*192 + 64 + tid]);
    }
    atomicAdd(&g_pool[(b << 9) + tid], a1);
    if (tid < 192) atomicAdd(&g_pool[(b << 9) + 256 + tid], a2);
    if (tid < 64)  atomicAdd(&g_pool[(b << 9) + 448 + tid], a3);
}
__global__ void softmax512() {
    int b = blockIdx.x, t = threadIdx.x;
    __shared__ float sh[512];
    float v = g_pool[(b << 9) + t] * (1.0f/65536.0f);
    sh[t] = v;
    __syncthreads();
    for (int st = 256; st > 0; st >>= 1) { if (t < st) sh[t] = fmaxf(sh[t], sh[t + st]); __syncthreads(); }
    float mx = sh[0];
    __syncthreads();
    float e = expf(v - mx);
    sh[t] = e;
    __syncthreads();
    for (int st = 256; st > 0; st >>= 1) { if (t < st) sh[t] += sh[t + st]; __syncthreads(); }
    float sum = sh[0];
    __syncthreads();
    g_pool[(b << 9) + t] = e / sum;
}
__global__ void cru_combine() {
    int i = blockIdx.x*256 + threadIdx.x;
    int t = i >> 8, c = i & 255;
    int b = t >> 16;
    float y1 = g_y1[i];
    float y2v;
    if (c < 192) y2v = g_y2[(size_t)t*192 + c];
    else {
        int nl = c - 192;
        y2v = bf2f(g_uls2[(size_t)t*192 + nl]) + bf2f(g_uls2[(size_t)t*192 + 64 + nl]);
    }
    g_ka[(size_t)t*256 + c] = g_pool[(b << 9) + c]*y1 + g_pool[(b << 9) + 256 + c]*y2v;
}

// ---------------- windowed attention ----------------
__global__ __launch_bounds__(64) void attn(const float* __restrict__ rel_pos) {
    int win = blockIdx.x, h = blockIdx.y, b = blockIdx.z;
    __shared__ __align__(16) float ksh[2048];
    __shared__ __align__(16) float vsh[2048];
    __shared__ float rp[225];
    int wy = win >> 5, wx = win & 31;
    int t0 = (b << 16) + (wy << 11) + (wx << 3);
    int tid = threadIdx.x;
    int hb = h << 5;
    for (int i = tid; i < 2048; i += 64) {
        int p = i >> 5, d = i & 31;
        int t = t0 + ((p >> 3) << 8) + (p & 7);
        ksh[i] = g_ka[(size_t)t*256 + hb + d];
        vsh[i] = g_v [(size_t)t*256 + hb + d];
    }
    for (int i = tid; i < 225; i += 64) rp[i] = rel_pos[h*225 + i];
    __syncthreads();
    int myt = t0 + ((tid >> 3) << 8) + (tid & 7);
    ull qp[16];
#pragma unroll
    for (int d = 0; d < 16; d++) {
        float2 qv = *(const float2*)&g_qa[(size_t)myt*256 + hb + 2*d];
        qp[d] = pack2(qv.x, qv.y);
    }
    int ph = tid >> 3, pw = tid & 7;
    bool lr = wy == 31, lc = wx == 31;
    ull zz = pack2(0.f, 0.f);
    float s[64];
#pragma unroll
    for (int qi = 0; qi < 64; qi++) {
        const ull* kp = (const ull*)&ksh[qi*32];
        ull dp = zz;
#pragma unroll
        for (int d = 0; d < 16; d++) ffma2(dp, qp[d], kp[d]);
        float dl, dh;
        unpack2(dp, dl, dh);
        int qh = qi >> 3, qw = qi & 7;
        float val = (dl + dh)*SCALE + rp[(ph - qh + 7)*15 + (pw - qw + 7)];
        if ((lr && ((ph < 4) != (qh < 4))) || (lc && ((pw < 4) != (qw < 4)))) val = -1e30f;
        s[qi] = val;
    }
    float mx = -1e30f;
#pragma unroll
    for (int qi = 0; qi < 64; qi++) mx = fmaxf(mx, s[qi]);
    float sum = 0.f;
#pragma unroll
    for (int qi = 0; qi < 64; qi++) { s[qi] = expf(s[qi] - mx); sum += s[qi]; }
    float inv = 1.0f / sum;
    ull accp[16];
#pragma unroll
    for (int d = 0; d < 16; d++) accp[d] = zz;
#pragma unroll
    for (int qi = 0; qi < 64; qi++) {
        ull wd = pack2(s[qi]*inv, s[qi]*inv);
        const ull* vp = (const ull*)&vsh[qi*32];
#pragma unroll
        for (int d = 0; d < 16; d++) ffma2(accp[d], wd, vp[d]);
    }
    float af[32];
#pragma unroll
    for (int d = 0; d < 16; d++) unpack2(accp[d], af[2*d], af[2*d+1]);
    __nv_bfloat16* dst = &g_atts[(size_t)myt*768];
#pragma unroll
    for (int d0 = 0; d0 < 32; d0 += 8) {
        __nv_bfloat16 hv[8], lv[8];
#pragma unroll
        for (int e = 0; e < 8; e++) {
            hv[e] = __float2bfloat16(af[d0 + e]);
            lv[e] = __float2bfloat16(af[d0 + e] - bf2f(hv[e]));
        }
        *(uint4*)&dst[hb + d0]       = *(uint4*)hv;
        *(uint4*)&dst[256 + hb + d0] = *(uint4*)lv;
        *(uint4*)&dst[512 + hb + d0] = *(uint4*)hv;
    }
}

// ---------------- final un-roll scatter to NCHW ----------------
__global__ __launch_bounds__(256) void unscatter(float* __restrict__ out) {
    __shared__ float s2[32][261];
    int bid = blockIdx.x;
    int b = bid >> 11, rem = bid & 2047;
    int hr = rem >> 3, w0 = (rem & 7) << 5;
    int tid = threadIdx.x;
    size_t tbase = (size_t)(b << 16) + (hr << 8) + w0;
    for (int i = 0; i < 8; i++) {
        int idx = (i << 8) + tid;
        int tw = idx >> 6, c4 = idx & 63;
        float4 v = *(const float4*)&g_qa[(tbase + tw)*256 + (c4 << 2)];
        s2[tw][(c4 << 2)]     = v.x;
        s2[tw][(c4 << 2) + 1] = v.y;
        s2[tw][(c4 << 2) + 2] = v.z;
        s2[tw][(c4 << 2) + 3] = v.w;
    }
    __syncthreads();
    int hs = ((hr + 4) & 255) << 8;
    for (int i = 0; i < 32; i++) {
        int idx = (i << 8) + tid;
        int c = idx >> 5, wp = idx & 31;
        out[(size_t)((b << 8) + c)*65536 + hs + ((w0 + wp + 4) & 255)] = s2[wp][c];
    }
}

// ---------------- launch ----------------
extern "C" void kernel_launch(void* const* d_in, const int* in_sizes, int n_in,
                              void* d_out, int out_size) {
    const float* x      = (const float*)d_in[0];
    const float* w_qkv  = (const float*)d_in[1];
    const float* b_qkv  = (const float*)d_in[2];
    const float* rel_pos= (const float*)d_in[3];
    const float* gn_w   = (const float*)d_in[4];
    const float* gn_b   = (const float*)d_in[5];
    const float* sq1    = (const float*)d_in[6];
    const float* sq2    = (const float*)d_in[7];
    const float* gwc    = (const float*)d_in[8];
    const float* gwc_b  = (const float*)d_in[9];
    const float* pwc1   = (const float*)d_in[10];
    const float* pwc2   = (const float*)d_in[11];
    const float* w_out  = (const float*)d_in[12];
    const float* b_out  = (const float*)d_in[13];
    float* out = (float*)d_out;

    __nv_bfloat16 *p_bq, *p_bout, *p_bsq, *p_bconv2, *p_bpwc2n, *p_xs, *p_ks, *p_atts, *p_uls2;
    cudaGetSymbolAddress((void**)&p_bq,     g_bq);
    cudaGetSymbolAddress((void**)&p_bout,   g_bout);
    cudaGetSymbolAddress((void**)&p_bsq,    g_bsq);
    cudaGetSymbolAddress((void**)&p_bconv2, g_bconv2);
    cudaGetSymbolAddress((void**)&p_bpwc2n, g_bpwc2n);
    cudaGetSymbolAddress((void**)&p_xs,     g_xs);
    cudaGetSymbolAddress((void**)&p_ks,     g_ks);
    cudaGetSymbolAddress((void**)&p_atts,   g_atts);
    cudaGetSymbolAddress((void**)&p_uls2,   g_uls2);

    const int DSM = 98304;
    cudaFuncSetAttribute(hgemmA<EQKVt>, cudaFuncAttributeMaxDynamicSharedMemorySize, DSM);
    cudaFuncSetAttribute(hgemmA<EOutT>, cudaFuncAttributeMaxDynamicSharedMemorySize, DSM);
    cudaFuncSetAttribute(hgemmA<ESQ>,   cudaFuncAttributeMaxDynamicSharedMemorySize, DSM);
    cudaFuncSetAttribute(hgemmA<EY2h>,  cudaFuncAttributeMaxDynamicSharedMemorySize, DSM);

    zero_small<<<4, 256>>>();                                          // 0
    prep_bw<<<(768*768 + 255)/256, 256>>>(w_qkv, p_bq, 768);           // 1
    xsplit<<<4096, 256>>>(x);                                          // 2
    hgemmA<EQKVt><<<dim3(6, 1024), 256, DSM>>>(p_xs, 768, p_bq, 768, 12, EQKVt{b_qkv});  // 3 (profiled)

    gn_stats<<<256, 256>>>();
    sum_gnw<<<1, 256>>>(gn_w);
    sru_elem<<<65536, 256>>>(gn_w, gn_b);

    prep_bsq<<<(128*768 + 255)/256, 256>>>(sq1, sq2);
    hgemmA<ESQ><<<dim3(1, 1024), 256, DSM>>>(p_ks, 768, p_bsq, 768, 12, ESQ{});
    prep_bconv2<<<(2*128*1088 + 255)/256, 256>>>(gwc, pwc1);
    hgemmS<<<dim3(1, 1024, 2), 256>>>(AConv2{}, p_bconv2, gwc_b);
    prep_bpwc2n<<<(256*192 + 255)/256, 256>>>(pwc2);
    hgemmA<EY2h><<<dim3(2, 1024), 256, DSM>>>(p_uls2, 192, p_bpwc2n, 192, 3, EY2h{});

    pool_kernel<<<512, 256>>>();
    softmax512<<<2, 512>>>();
    cru_combine<<<131072, 256>>>();

    attn<<<dim3(1024, 8, 2), 64>>>(rel_pos);
    prep_bw<<<(256*768 + 255)/256, 256>>>(w_out, p_bout, 256);
    hgemmA<EOutT><<<dim3(2, 1024), 256, DSM>>>(p_atts, 768, p_bout, 768, 12, EOutT{b_out});
    unscatter<<<4096, 256>>>(out);
}